// round 14
// baseline (speedup 1.0000x reference)
#include <cuda_runtime.h>
#include <math.h>
#include <stdint.h>

#define NN   50000
#define NE   800000
#define DIN  256
#define HC1  512
#define HC2  256
#define NEG_SLOPE 0.2f

// ---------------- scratch (device globals; no allocation allowed) -------------
__device__ float g_aggx[NN * DIN];
__device__ float g_r1[NN * HC1];
__device__ float g_hrelu[NN * HC1];
__device__ float g_h2[NN * HC2];
__device__ float g_r2[NN * HC2];
__device__ float g_g2[NN * HC2];
__device__ float g_m1[NN * HC2];
__device__ float g_m2[NN * HC2];
__device__ float g_as[NN];
__device__ float g_ad[NN];
__device__ float g_cs[DIN];          // W1 @ att_src1
__device__ float g_cd[DIN];          // W1 @ att_dst1
__device__ float g_cs2[HC1];         // W2 @ att_src2
__device__ float g_cd2[HC1];         // W2 @ att_dst2
__device__ int   g_src[NE];
__device__ int   g_dst[NE];
__device__ int   g_csr[NE];
__device__ int   g_deg[NN];
__device__ int   g_cur[NN];
__device__ int   g_inc[NN];
__device__ int   g_bsum[256];
__device__ int   g_rowptr[NN + 1];
__device__ int   g_is64;

// ---------------- edge dtype detection + conversion ---------------------------
__global__ void detect_dtype(const int* __restrict__ ei) {
    __shared__ int nz;
    if (threadIdx.x == 0) nz = 0;
    __syncthreads();
    for (int t = threadIdx.x; t < 1024; t += blockDim.x) {
        long long pos = 1 + (long long)t * ((2LL * NE - 2) / 1024);
        pos |= 1;
        if (ei[pos] != 0) atomicExch(&nz, 1);
    }
    __syncthreads();
    if (threadIdx.x == 0) g_is64 = (nz == 0) ? 1 : 0;
}

__global__ void zero_build() {
    int i = blockIdx.x * blockDim.x + threadIdx.x;
    if (i < NN) { g_deg[i] = 0; g_cur[i] = 0; }
}

__global__ void convert_edges_count(const void* __restrict__ eiv) {
    int i = blockIdx.x * blockDim.x + threadIdx.x;
    if (i >= NE) return;
    int s, d;
    if (g_is64) {
        const long long* e = (const long long*)eiv;
        s = (int)e[i];
        d = (int)e[NE + i];
    } else {
        const int* e = (const int*)eiv;
        s = e[i];
        d = e[NE + i];
    }
    g_src[i] = s;
    g_dst[i] = d;
    atomicAdd(&g_deg[d], 1);
}

__global__ void scan_chunk() {
    __shared__ int s[1024];
    int tid = threadIdx.x;
    int i = blockIdx.x * 1024 + tid;
    int v = (i < NN) ? g_deg[i] : 0;
    s[tid] = v;
    __syncthreads();
    for (int off = 1; off < 1024; off <<= 1) {
        int t = (tid >= off) ? s[tid - off] : 0;
        __syncthreads();
        s[tid] += t;
        __syncthreads();
    }
    if (i < NN) g_inc[i] = s[tid];
    if (tid == 1023) g_bsum[blockIdx.x] = s[1023];
}

__global__ void scan_bsums(int nb) {
    if (threadIdx.x == 0 && blockIdx.x == 0) {
        int run = 0;
        for (int i = 0; i < nb; i++) { int v = g_bsum[i]; g_bsum[i] = run; run += v; }
    }
}

__global__ void finalize_rowptr() {
    int i = blockIdx.x * 1024 + threadIdx.x;
    if (i < NN) g_rowptr[i + 1] = g_inc[i] + g_bsum[blockIdx.x];
    if (i == 0) g_rowptr[0] = 0;
}

__global__ void scatter_csr() {
    int i = blockIdx.x * blockDim.x + threadIdx.x;
    if (i < NE) {
        int d = g_dst[i];
        int p = g_rowptr[d] + atomicAdd(&g_cur[d], 1);
        g_csr[p] = g_src[i];
    }
}

// ---------------- collapsed attention vectors: out = W @ attvec ----------------
__global__ void precompute_att(const float* __restrict__ W,
                               const float* __restrict__ avec,
                               const float* __restrict__ dvec,
                               float* __restrict__ outS,
                               float* __restrict__ outD,
                               int K, int H)
{
    int wk = (blockIdx.x * blockDim.x + threadIdx.x) >> 5;
    int lane = threadIdx.x & 31;
    if (wk >= K) return;
    const float* wr = W + (size_t)wk * H;
    float s1 = 0.f, s2 = 0.f;
    for (int j = lane; j < H; j += 32) {
        float v = wr[j];
        s1 += v * avec[j];
        s2 += v * dvec[j];
    }
#pragma unroll
    for (int o = 16; o; o >>= 1) {
        s1 += __shfl_down_sync(0xffffffffu, s1, o);
        s2 += __shfl_down_sync(0xffffffffu, s2, o);
    }
    if (lane == 0) { outS[wk] = s1; outD[wk] = s2; }
}

// ---------------- TF32 tensor-core GEMM, cp.async 2-stage, BK=32 ---------------
__device__ __forceinline__ void mma_tf32(float d[4], const uint32_t a[4],
                                         const uint32_t b[2], const float c[4]) {
    asm volatile(
        "mma.sync.aligned.m16n8k8.row.col.f32.tf32.tf32.f32 "
        "{%0,%1,%2,%3},{%4,%5,%6,%7},{%8,%9},{%10,%11,%12,%13};\n"
        : "=f"(d[0]), "=f"(d[1]), "=f"(d[2]), "=f"(d[3])
        : "r"(a[0]), "r"(a[1]), "r"(a[2]), "r"(a[3]),
          "r"(b[0]), "r"(b[1]),
          "f"(c[0]), "f"(c[1]), "f"(c[2]), "f"(c[3]));
}

#define AST 36
#define BST 136
#define A_SZ (128 * AST)
#define B_SZ (32 * BST)
#define GEMM_SMEM ((2 * A_SZ + 2 * B_SZ) * 4)

#define CP_ASYNC16(dst_u32, src_ptr, srcsz) \
    asm volatile("cp.async.cg.shared.global [%0], [%1], 16, %2;\n" \
                 :: "r"(dst_u32), "l"(src_ptr), "r"(srcsz))
#define CP_COMMIT() asm volatile("cp.async.commit_group;\n")
#define CP_WAIT1()  asm volatile("cp.async.wait_group 1;\n")

__global__ __launch_bounds__(256) void gemm_tf32(
    const float* __restrict__ A,
    const float* __restrict__ B1, const float* __restrict__ B2,
    const float* __restrict__ bias1, const float* __restrict__ bias2,
    const float* __restrict__ res1, const float* __restrict__ res2,
    float* __restrict__ C1, float* __restrict__ C2,
    int M, int N, int K, int relu)
{
    extern __shared__ float sm[];
    float* Asm = sm;
    float* Bsm = sm + 2 * A_SZ;

    const int tid  = threadIdx.x;
    const int lane = tid & 31;
    const int warp = tid >> 5;
    const int g    = lane >> 2;
    const int t4   = lane & 3;
    const int wm = (warp & 1) * 64;
    const int wn = (warp >> 1) * 32;

    const int nb = N >> 7;
    const int half = (B2 != nullptr && (int)blockIdx.x >= nb) ? 1 : 0;
    const float* B     = half ? B2    : B1;
    const float* bias  = half ? bias2 : bias1;
    const float* resid = half ? res2  : res1;
    float*       C     = half ? C2    : C1;
    const int col0 = (blockIdx.x - half * nb) * 128;
    const int row0 = blockIdx.y * 128;

    const int a_rb = tid >> 3;
    const int a_q  = (tid & 7) << 2;
    const int b_kb = tid >> 5;
    const int b_nc = (tid & 31) << 2;

    const uint32_t sA0 = (uint32_t)__cvta_generic_to_shared(Asm)
                       + (uint32_t)(a_rb * AST + a_q) * 4;
    const uint32_t sB0 = (uint32_t)__cvta_generic_to_shared(Bsm)
                       + (uint32_t)(b_kb * BST + b_nc) * 4;
    const uint32_t aBufStride = A_SZ * 4;
    const uint32_t bBufStride = B_SZ * 4;
    const uint32_t aSlot = 32 * AST * 4;
    const uint32_t bSlot = 8 * BST * 4;

    const float* aBase = A + (size_t)(row0 + a_rb) * K + a_q;
    const float* bBase = B + (size_t)b_kb * N + col0 + b_nc;
    const size_t aGStride = (size_t)32 * K;
    const size_t bGStride = (size_t)8 * N;

    int az[4];
#pragma unroll
    for (int t = 0; t < 4; t++) az[t] = (row0 + a_rb + t * 32 < M) ? 16 : 0;

    float acc[4][4][4];
#pragma unroll
    for (int mi = 0; mi < 4; mi++)
#pragma unroll
        for (int ni = 0; ni < 4; ni++)
#pragma unroll
            for (int q = 0; q < 4; q++) acc[mi][ni][q] = 0.f;

    const int NT = K >> 5;

#define LOAD_TILE(buf, k0)                                                    \
    do {                                                                      \
        _Pragma("unroll")                                                     \
        for (int t = 0; t < 4; t++) {                                         \
            CP_ASYNC16(sA0 + (buf) * aBufStride + t * aSlot,                  \
                       aBase + t * aGStride + (k0), az[t]);                   \
            CP_ASYNC16(sB0 + (buf) * bBufStride + t * bSlot,                  \
                       bBase + t * bGStride + (size_t)(k0) * N, 16);          \
        }                                                                     \
    } while (0)

    LOAD_TILE(0, 0);
    CP_COMMIT();

    for (int it = 0; it < NT; it++) {
        const int cur = it & 1;
        if (it + 1 < NT) LOAD_TILE(cur ^ 1, (it + 1) << 5);
        CP_COMMIT();
        CP_WAIT1();
        __syncthreads();

        const uint32_t* Au = (const uint32_t*)(Asm + cur * A_SZ);
        const uint32_t* Bu = (const uint32_t*)(Bsm + cur * B_SZ);
#pragma unroll
        for (int ks = 0; ks < 4; ks++) {
            const int kb = ks * 8;
            uint32_t af[4][4];
#pragma unroll
            for (int mi = 0; mi < 4; mi++) {
                int r = wm + mi * 16 + g;
                af[mi][0] = Au[r * AST + kb + t4];
                af[mi][1] = Au[(r + 8) * AST + kb + t4];
                af[mi][2] = Au[r * AST + kb + t4 + 4];
                af[mi][3] = Au[(r + 8) * AST + kb + t4 + 4];
            }
            uint32_t bf[4][2];
#pragma unroll
            for (int ni = 0; ni < 4; ni++) {
                int n = wn + ni * 8 + g;
                bf[ni][0] = Bu[(kb + t4) * BST + n];
                bf[ni][1] = Bu[(kb + t4 + 4) * BST + n];
            }
#pragma unroll
            for (int mi = 0; mi < 4; mi++)
#pragma unroll
                for (int ni = 0; ni < 4; ni++)
                    mma_tf32(acc[mi][ni], af[mi], bf[ni], acc[mi][ni]);
        }
        __syncthreads();
    }

    // epilogue
#pragma unroll
    for (int mi = 0; mi < 4; mi++) {
        int r_lo = row0 + wm + mi * 16 + g;
        int r_hi = r_lo + 8;
#pragma unroll
        for (int ni = 0; ni < 4; ni++) {
            int c = col0 + wn + ni * 8 + t4 * 2;
            float badd0 = bias ? bias[c]     : 0.f;
            float badd1 = bias ? bias[c + 1] : 0.f;
            float v0 = acc[mi][ni][0] + badd0;
            float v1 = acc[mi][ni][1] + badd1;
            float v2 = acc[mi][ni][2] + badd0;
            float v3 = acc[mi][ni][3] + badd1;
            if (resid) {
                if (r_lo < M) {
                    v0 += resid[(size_t)r_lo * N + c];
                    v1 += resid[(size_t)r_lo * N + c + 1];
                }
                if (r_hi < M) {
                    v2 += resid[(size_t)r_hi * N + c];
                    v3 += resid[(size_t)r_hi * N + c + 1];
                }
            }
            if (relu) {
                v0 = fmaxf(v0, 0.f); v1 = fmaxf(v1, 0.f);
                v2 = fmaxf(v2, 0.f); v3 = fmaxf(v3, 0.f);
            }
            if (r_lo < M) {
                C[(size_t)r_lo * N + c]     = v0;
                C[(size_t)r_lo * N + c + 1] = v1;
            }
            if (r_hi < M) {
                C[(size_t)r_hi * N + c]     = v2;
                C[(size_t)r_hi * N + c + 1] = v3;
            }
        }
    }
#undef LOAD_TILE
}

// ---------------- attention scores (float4 loads) ------------------------------
__global__ void attn_scores(const float* __restrict__ h,
                            const float* __restrict__ av, const float* __restrict__ dv,
                            int H)
{
    int warp = (blockIdx.x * blockDim.x + threadIdx.x) >> 5;
    int lane = threadIdx.x & 31;
    if (warp >= NN) return;
    const float4* hr = (const float4*)(h + (size_t)warp * H);
    const float4* a4 = (const float4*)av;
    const float4* d4 = (const float4*)dv;
    float s1 = 0.f, s2 = 0.f;
    for (int k = lane; k < (H >> 2); k += 32) {
        float4 v = hr[k], a = a4[k], d = d4[k];
        s1 += v.x * a.x + v.y * a.y + v.z * a.z + v.w * a.w;
        s2 += v.x * d.x + v.y * d.y + v.z * d.z + v.w * d.w;
    }
#pragma unroll
    for (int o = 16; o; o >>= 1) {
        s1 += __shfl_down_sync(0xffffffffu, s1, o);
        s2 += __shfl_down_sync(0xffffffffu, s2, o);
    }
    if (lane == 0) { g_as[warp] = s1; g_ad[warp] = s2; }
}

// ---------------- GAT aggregation: warp per node in [nodeBeg,nodeEnd) ----------
// 4-edge unroll (MLP=8); no-max softmax; resid == nullptr -> raw agg mode.
template <int H, bool RELU>
__global__ __launch_bounds__(256) void gat_agg_warp(
    const float* __restrict__ h, const float* __restrict__ resid,
    const float* __restrict__ bias, float* __restrict__ out,
    int nodeBeg, int nodeEnd)
{
    const int node = nodeBeg + (int)((blockIdx.x * blockDim.x + threadIdx.x) >> 5);
    const int lane = threadIdx.x & 31;
    if (node >= nodeEnd) return;
    const int beg = g_rowptr[node], end = g_rowptr[node + 1];
    const float adv = g_ad[node];
    constexpr int V4 = H / 128;

    float4 acc[V4];
#pragma unroll
    for (int v = 0; v < V4; v++) acc[v] = make_float4(0.f, 0.f, 0.f, 0.f);
    float ssum = 0.f;

    for (int p = beg; p < end; p += 32) {
        int j = p + lane;
        float w = 0.f;
        int s = 0;
        if (j < end) {
            s = g_csr[j];
            float z = g_as[s] + adv;
            z = z > 0.f ? z : NEG_SLOPE * z;
            w = __expf(z);
        }
        ssum += w;
        int cnt = min(32, end - p);
        int t = 0;
        for (; t + 3 < cnt; t += 4) {
            float wt0 = __shfl_sync(0xffffffffu, w, t);
            int   st0 = __shfl_sync(0xffffffffu, s, t);
            float wt1 = __shfl_sync(0xffffffffu, w, t + 1);
            int   st1 = __shfl_sync(0xffffffffu, s, t + 1);
            float wt2 = __shfl_sync(0xffffffffu, w, t + 2);
            int   st2 = __shfl_sync(0xffffffffu, s, t + 2);
            float wt3 = __shfl_sync(0xffffffffu, w, t + 3);
            int   st3 = __shfl_sync(0xffffffffu, s, t + 3);
            const float4* h0 = (const float4*)(h + (size_t)st0 * H);
            const float4* h1 = (const float4*)(h + (size_t)st1 * H);
            const float4* h2 = (const float4*)(h + (size_t)st2 * H);
            const float4* h3 = (const float4*)(h + (size_t)st3 * H);
#pragma unroll
            for (int v = 0; v < V4; v++) {
                int i = lane + v * 32;
                float4 a0 = h0[i], a1 = h1[i], a2 = h2[i], a3 = h3[i];
                acc[v].x += wt0 * a0.x + wt1 * a1.x + wt2 * a2.x + wt3 * a3.x;
                acc[v].y += wt0 * a0.y + wt1 * a1.y + wt2 * a2.y + wt3 * a3.y;
                acc[v].z += wt0 * a0.z + wt1 * a1.z + wt2 * a2.z + wt3 * a3.z;
                acc[v].w += wt0 * a0.w + wt1 * a1.w + wt2 * a2.w + wt3 * a3.w;
            }
        }
        for (; t < cnt; t++) {
            float wt = __shfl_sync(0xffffffffu, w, t);
            int   st = __shfl_sync(0xffffffffu, s, t);
            const float4* hr = (const float4*)(h + (size_t)st * H);
#pragma unroll
            for (int v = 0; v < V4; v++) {
                int i = lane + v * 32;
                float4 hv = hr[i];
                acc[v].x += wt * hv.x;
                acc[v].y += wt * hv.y;
                acc[v].z += wt * hv.z;
                acc[v].w += wt * hv.w;
            }
        }
    }
#pragma unroll
    for (int o = 16; o; o >>= 1) ssum += __shfl_xor_sync(0xffffffffu, ssum, o);
    float inv = 1.f / (ssum + 1e-16f);

    float4* o4 = (float4*)(out + (size_t)node * H);
    if (resid) {
        const float4* r4 = (const float4*)(resid + (size_t)node * H);
        const float4* b4 = (const float4*)bias;
#pragma unroll
        for (int v = 0; v < V4; v++) {
            int i = lane + v * 32;
            float4 rr = r4[i], bb = b4[i];
            float4 ov;
            ov.x = acc[v].x * inv + bb.x + rr.x;
            ov.y = acc[v].y * inv + bb.y + rr.y;
            ov.z = acc[v].z * inv + bb.z + rr.z;
            ov.w = acc[v].w * inv + bb.w + rr.w;
            if (RELU) {
                ov.x = fmaxf(ov.x, 0.f); ov.y = fmaxf(ov.y, 0.f);
                ov.z = fmaxf(ov.z, 0.f); ov.w = fmaxf(ov.w, 0.f);
            }
            o4[i] = ov;
        }
    } else {
#pragma unroll
        for (int v = 0; v < V4; v++) {
            int i = lane + v * 32;
            float4 ov;
            ov.x = acc[v].x * inv;
            ov.y = acc[v].y * inv;
            ov.z = acc[v].z * inv;
            ov.w = acc[v].w * inv;
            o4[i] = ov;
        }
    }
}

// ---------------- classifier + softmax (warp per node) -------------------------
__global__ void classifier_softmax(const float* __restrict__ h,
                                   const float* __restrict__ w,
                                   const float* __restrict__ b,
                                   float* __restrict__ out)
{
    int warp = (blockIdx.x * blockDim.x + threadIdx.x) >> 5;
    int lane = threadIdx.x & 31;
    if (warp >= NN) return;
    const float* hr = h + (size_t)warp * HC2;
    float d0 = 0, d1 = 0, d2 = 0, d3 = 0, d4 = 0;
    for (int k = lane; k < HC2; k += 32) {
        float v = hr[k];
        d0 += v * w[k * 5 + 0];
        d1 += v * w[k * 5 + 1];
        d2 += v * w[k * 5 + 2];
        d3 += v * w[k * 5 + 3];
        d4 += v * w[k * 5 + 4];
    }
#pragma unroll
    for (int o = 16; o; o >>= 1) {
        d0 += __shfl_down_sync(0xffffffffu, d0, o);
        d1 += __shfl_down_sync(0xffffffffu, d1, o);
        d2 += __shfl_down_sync(0xffffffffu, d2, o);
        d3 += __shfl_down_sync(0xffffffffu, d3, o);
        d4 += __shfl_down_sync(0xffffffffu, d4, o);
    }
    if (lane == 0) {
        d0 += b[0]; d1 += b[1]; d2 += b[2]; d3 += b[3]; d4 += b[4];
        float mx = fmaxf(fmaxf(fmaxf(d0, d1), fmaxf(d2, d3)), d4);
        float e0 = expf(d0 - mx), e1 = expf(d1 - mx), e2 = expf(d2 - mx),
              e3 = expf(d3 - mx), e4 = expf(d4 - mx);
        float inv = 1.f / (e0 + e1 + e2 + e3 + e4);
        out[warp * 5 + 0] = e0 * inv;
        out[warp * 5 + 1] = e1 * inv;
        out[warp * 5 + 2] = e2 * inv;
        out[warp * 5 + 3] = e3 * inv;
        out[warp * 5 + 4] = e4 * inv;
    }
}

// ---------------- launch -------------------------------------------------------
extern "C" void kernel_launch(void* const* d_in, const int* in_sizes, int n_in,
                              void* d_out, int out_size)
{
    const float* x        = (const float*)d_in[0];
    const void*  ei       = d_in[1];
    const float* W1       = (const float*)d_in[2];
    const float* att_src1 = (const float*)d_in[3];
    const float* att_dst1 = (const float*)d_in[4];
    const float* b_conv1  = (const float*)d_in[5];
    const float* A1       = (const float*)d_in[6];
    const float* b1       = (const float*)d_in[7];
    const float* W2       = (const float*)d_in[8];
    const float* att_src2 = (const float*)d_in[9];
    const float* att_dst2 = (const float*)d_in[10];
    const float* b_conv2  = (const float*)d_in[11];
    const float* A2       = (const float*)d_in[12];
    const float* b2       = (const float*)d_in[13];
    const float* Hw1      = (const float*)d_in[14];
    const float* Hb1      = (const float*)d_in[15];
    const float* Hw2      = (const float*)d_in[16];
    const float* Hb2      = (const float*)d_in[17];
    const float* Hw3      = (const float*)d_in[18];
    const float* Hb3      = (const float*)d_in[19];
    const float* fcw      = (const float*)d_in[20];
    const float* fcb      = (const float*)d_in[21];
    float* out = (float*)d_out;

    float *p_aggx, *p_r1, *p_hrelu, *p_h2, *p_r2, *p_g2, *p_m1, *p_m2;
    float *p_cs, *p_cd, *p_cs2, *p_cd2;
    cudaGetSymbolAddress((void**)&p_aggx,  g_aggx);
    cudaGetSymbolAddress((void**)&p_r1,    g_r1);
    cudaGetSymbolAddress((void**)&p_hrelu, g_hrelu);
    cudaGetSymbolAddress((void**)&p_h2,    g_h2);
    cudaGetSymbolAddress((void**)&p_r2,    g_r2);
    cudaGetSymbolAddress((void**)&p_g2,    g_g2);
    cudaGetSymbolAddress((void**)&p_m1,    g_m1);
    cudaGetSymbolAddress((void**)&p_m2,    g_m2);
    cudaGetSymbolAddress((void**)&p_cs,    g_cs);
    cudaGetSymbolAddress((void**)&p_cd,    g_cd);
    cudaGetSymbolAddress((void**)&p_cs2,   g_cs2);
    cudaGetSymbolAddress((void**)&p_cd2,   g_cd2);

    cudaFuncSetAttribute(gemm_tf32, cudaFuncAttributeMaxDynamicSharedMemorySize,
                         GEMM_SMEM);

    const int NB1024 = (NN + 1023) / 1024;
    const int MB = (NN + 127) / 128;
    const int warps_grid = (NN * 32 + 255) / 256;
    const int NHALF = NN / 2;
    const int half_grid = (NHALF * 32 + 255) / 256;

    // single side stream (proven capture topology)
    cudaStream_t s1;
    cudaStreamCreateWithFlags(&s1, cudaStreamNonBlocking);
    cudaEvent_t e_fork, e_att1, e_join, e_h, e_att2;
    cudaEventCreateWithFlags(&e_fork, cudaEventDisableTiming);
    cudaEventCreateWithFlags(&e_att1, cudaEventDisableTiming);
    cudaEventCreateWithFlags(&e_join, cudaEventDisableTiming);
    cudaEventCreateWithFlags(&e_h,    cudaEventDisableTiming);
    cudaEventCreateWithFlags(&e_att2, cudaEventDisableTiming);

    cudaEventRecord(e_fork, 0);
    cudaStreamWaitEvent(s1, e_fork, 0);

    // ---- side stream: CSR build only ----
    detect_dtype<<<1, 256, 0, s1>>>((const int*)ei);
    zero_build<<<(NN + 255) / 256, 256, 0, s1>>>();
    convert_edges_count<<<(NE + 255) / 256, 256, 0, s1>>>(ei);
    scan_chunk<<<NB1024, 1024, 0, s1>>>();
    scan_bsums<<<1, 32, 0, s1>>>(NB1024);
    finalize_rowptr<<<NB1024, 1024, 0, s1>>>();
    scatter_csr<<<(NE + 255) / 256, 256, 0, s1>>>();

    // ---- main: layer-1 attention (no CSR needed), then r1 GEMM ----
    precompute_att<<<(DIN * 32 + 255) / 256, 256>>>(
        W1, att_src1, att_dst1, p_cs, p_cd, DIN, HC1);
    attn_scores<<<warps_grid, 256>>>(x, p_cs, p_cd, DIN);
    cudaEventRecord(e_att1, 0);

    gemm_tf32<<<dim3(HC1 / 128, MB), 256, GEMM_SMEM>>>(
        x, A1, nullptr, b1, nullptr, nullptr, nullptr, p_r1, nullptr,
        NN, HC1, DIN, 0);

    // ---- agg1 split across both streams (disjoint node ranges) ----
    cudaStreamWaitEvent(s1, e_att1, 0);
    gat_agg_warp<DIN, false><<<half_grid, 256, 0, s1>>>(
        x, nullptr, nullptr, p_aggx, 0, NHALF);
    cudaEventRecord(e_join, s1);

    // main's half runs right after r1 GEMM (CSR done by then)
    gat_agg_warp<DIN, false><<<(warps_grid - half_grid) + 1, 256>>>(
        x, nullptr, nullptr, p_aggx, NHALF, NN);

    cudaStreamWaitEvent(0, e_join, 0);

    // hrelu = relu(aggx@W1 + b_conv1 + r1)
    gemm_tf32<<<dim3(HC1 / 128, MB), 256, GEMM_SMEM>>>(
        p_aggx, W1, nullptr, b_conv1, nullptr, p_r1, nullptr, p_hrelu, nullptr,
        NN, HC1, DIN, 1);
    cudaEventRecord(e_h, 0);

    // ---- side stream: layer-2 collapsed attention on hrelu ----
    cudaStreamWaitEvent(s1, e_h, 0);
    precompute_att<<<(HC1 * 32 + 255) / 256, 256, 0, s1>>>(
        W2, att_src2, att_dst2, p_cs2, p_cd2, HC1, HC2);
    attn_scores<<<warps_grid, 256, 0, s1>>>(p_hrelu, p_cs2, p_cd2, HC1);
    cudaEventRecord(e_att2, s1);

    // ---- layer 2 dual GEMM (main, concurrent with attn2) ----
    gemm_tf32<<<dim3(2 * HC2 / 128, MB), 256, GEMM_SMEM>>>(
        p_hrelu, W2, A2, nullptr, b2, nullptr, nullptr, p_h2, p_r2,
        NN, HC2, HC1, 0);

    cudaStreamWaitEvent(0, e_att2, 0);
    gat_agg_warp<HC2, false><<<warps_grid, 256>>>(
        p_h2, p_r2, b_conv2, p_g2, 0, NN);

    // ---- MLP ----
    gemm_tf32<<<dim3(HC2 / 128, MB), 256, GEMM_SMEM>>>(
        p_g2, Hw1, nullptr, Hb1, nullptr, nullptr, nullptr, p_m1, nullptr,
        NN, HC2, HC2, 1);
    gemm_tf32<<<dim3(HC2 / 128, MB), 256, GEMM_SMEM>>>(
        p_m1, Hw2, nullptr, Hb2, nullptr, nullptr, nullptr, p_m2, nullptr,
        NN, HC2, HC2, 1);
    gemm_tf32<<<dim3(HC2 / 128, MB), 256, GEMM_SMEM>>>(
        p_m2, Hw3, nullptr, Hb3, nullptr, nullptr, nullptr, p_m1, nullptr,
        NN, HC2, HC2, 1);

    // ---- classifier + softmax ----
    classifier_softmax<<<warps_grid, 256>>>(p_m1, fcw, fcb, out);
}

// round 15
// speedup vs baseline: 1.0131x; 1.0131x over previous
#include <cuda_runtime.h>
#include <math.h>
#include <stdint.h>

#define NN   50000
#define NE   800000
#define DIN  256
#define HC1  512
#define HC2  256
#define NEG_SLOPE 0.2f

// ---------------- scratch (device globals; no allocation allowed) -------------
__device__ float g_aggx[NN * DIN];
__device__ float g_r1[NN * HC1];
__device__ float g_hrelu[NN * HC1];
__device__ float g_h2[NN * HC2];
__device__ float g_r2[NN * HC2];
__device__ float g_g2[NN * HC2];
__device__ float g_m1[NN * HC2];
__device__ float g_m2[NN * HC2];
__device__ float g_as[NN];
__device__ float g_ad[NN];
__device__ float g_cs[DIN];          // W1 @ att_src1
__device__ float g_cd[DIN];          // W1 @ att_dst1
__device__ float g_cs2[HC1];         // W2 @ att_src2
__device__ float g_cd2[HC1];         // W2 @ att_dst2
__device__ int   g_src[NE];
__device__ int   g_dst[NE];
__device__ int   g_csr[NE];
__device__ int   g_deg[NN];
__device__ int   g_cur[NN];
__device__ int   g_inc[NN];
__device__ int   g_bsum[256];
__device__ int   g_rowptr[NN + 1];
__device__ int   g_is64;

// ---------------- edge dtype detection + conversion ---------------------------
__global__ void detect_dtype(const int* __restrict__ ei) {
    __shared__ int nz;
    if (threadIdx.x == 0) nz = 0;
    __syncthreads();
    for (int t = threadIdx.x; t < 1024; t += blockDim.x) {
        long long pos = 1 + (long long)t * ((2LL * NE - 2) / 1024);
        pos |= 1;
        if (ei[pos] != 0) atomicExch(&nz, 1);
    }
    __syncthreads();
    if (threadIdx.x == 0) g_is64 = (nz == 0) ? 1 : 0;
}

__global__ void zero_build() {
    int i = blockIdx.x * blockDim.x + threadIdx.x;
    if (i < NN) { g_deg[i] = 0; g_cur[i] = 0; }
}

__global__ void convert_edges_count(const void* __restrict__ eiv) {
    int i = blockIdx.x * blockDim.x + threadIdx.x;
    if (i >= NE) return;
    int s, d;
    if (g_is64) {
        const long long* e = (const long long*)eiv;
        s = (int)e[i];
        d = (int)e[NE + i];
    } else {
        const int* e = (const int*)eiv;
        s = e[i];
        d = e[NE + i];
    }
    g_src[i] = s;
    g_dst[i] = d;
    atomicAdd(&g_deg[d], 1);
}

__global__ void scan_chunk() {
    __shared__ int s[1024];
    int tid = threadIdx.x;
    int i = blockIdx.x * 1024 + tid;
    int v = (i < NN) ? g_deg[i] : 0;
    s[tid] = v;
    __syncthreads();
    for (int off = 1; off < 1024; off <<= 1) {
        int t = (tid >= off) ? s[tid - off] : 0;
        __syncthreads();
        s[tid] += t;
        __syncthreads();
    }
    if (i < NN) g_inc[i] = s[tid];
    if (tid == 1023) g_bsum[blockIdx.x] = s[1023];
}

__global__ void scan_bsums(int nb) {
    if (threadIdx.x == 0 && blockIdx.x == 0) {
        int run = 0;
        for (int i = 0; i < nb; i++) { int v = g_bsum[i]; g_bsum[i] = run; run += v; }
    }
}

__global__ void finalize_rowptr() {
    int i = blockIdx.x * 1024 + threadIdx.x;
    if (i < NN) g_rowptr[i + 1] = g_inc[i] + g_bsum[blockIdx.x];
    if (i == 0) g_rowptr[0] = 0;
}

__global__ void scatter_csr() {
    int i = blockIdx.x * blockDim.x + threadIdx.x;
    if (i < NE) {
        int d = g_dst[i];
        int p = g_rowptr[d] + atomicAdd(&g_cur[d], 1);
        g_csr[p] = g_src[i];
    }
}

// ---------------- collapsed attention vectors: out = W @ attvec ----------------
__global__ void precompute_att(const float* __restrict__ W,
                               const float* __restrict__ avec,
                               const float* __restrict__ dvec,
                               float* __restrict__ outS,
                               float* __restrict__ outD,
                               int K, int H)
{
    int wk = (blockIdx.x * blockDim.x + threadIdx.x) >> 5;
    int lane = threadIdx.x & 31;
    if (wk >= K) return;
    const float* wr = W + (size_t)wk * H;
    float s1 = 0.f, s2 = 0.f;
    for (int j = lane; j < H; j += 32) {
        float v = wr[j];
        s1 += v * avec[j];
        s2 += v * dvec[j];
    }
#pragma unroll
    for (int o = 16; o; o >>= 1) {
        s1 += __shfl_down_sync(0xffffffffu, s1, o);
        s2 += __shfl_down_sync(0xffffffffu, s2, o);
    }
    if (lane == 0) { outS[wk] = s1; outD[wk] = s2; }
}

// ---------------- TF32 tensor-core GEMM, cp.async 2-stage, BK=32 ---------------
__device__ __forceinline__ void mma_tf32(float d[4], const uint32_t a[4],
                                         const uint32_t b[2], const float c[4]) {
    asm volatile(
        "mma.sync.aligned.m16n8k8.row.col.f32.tf32.tf32.f32 "
        "{%0,%1,%2,%3},{%4,%5,%6,%7},{%8,%9},{%10,%11,%12,%13};\n"
        : "=f"(d[0]), "=f"(d[1]), "=f"(d[2]), "=f"(d[3])
        : "r"(a[0]), "r"(a[1]), "r"(a[2]), "r"(a[3]),
          "r"(b[0]), "r"(b[1]),
          "f"(c[0]), "f"(c[1]), "f"(c[2]), "f"(c[3]));
}

#define AST 36
#define BST 136
#define A_SZ (128 * AST)
#define B_SZ (32 * BST)
#define GEMM_SMEM ((2 * A_SZ + 2 * B_SZ) * 4)

#define CP_ASYNC16(dst_u32, src_ptr, srcsz) \
    asm volatile("cp.async.cg.shared.global [%0], [%1], 16, %2;\n" \
                 :: "r"(dst_u32), "l"(src_ptr), "r"(srcsz))
#define CP_COMMIT() asm volatile("cp.async.commit_group;\n")
#define CP_WAIT1()  asm volatile("cp.async.wait_group 1;\n")

__global__ __launch_bounds__(256) void gemm_tf32(
    const float* __restrict__ A,
    const float* __restrict__ B1, const float* __restrict__ B2,
    const float* __restrict__ bias1, const float* __restrict__ bias2,
    const float* __restrict__ res1, const float* __restrict__ res2,
    float* __restrict__ C1, float* __restrict__ C2,
    int M, int N, int K, int relu)
{
    extern __shared__ float sm[];
    float* Asm = sm;
    float* Bsm = sm + 2 * A_SZ;

    const int tid  = threadIdx.x;
    const int lane = tid & 31;
    const int warp = tid >> 5;
    const int g    = lane >> 2;
    const int t4   = lane & 3;
    const int wm = (warp & 1) * 64;
    const int wn = (warp >> 1) * 32;

    const int nb = N >> 7;
    const int half = (B2 != nullptr && (int)blockIdx.x >= nb) ? 1 : 0;
    const float* B     = half ? B2    : B1;
    const float* bias  = half ? bias2 : bias1;
    const float* resid = half ? res2  : res1;
    float*       C     = half ? C2    : C1;
    const int col0 = (blockIdx.x - half * nb) * 128;
    const int row0 = blockIdx.y * 128;

    const int a_rb = tid >> 3;
    const int a_q  = (tid & 7) << 2;
    const int b_kb = tid >> 5;
    const int b_nc = (tid & 31) << 2;

    const uint32_t sA0 = (uint32_t)__cvta_generic_to_shared(Asm)
                       + (uint32_t)(a_rb * AST + a_q) * 4;
    const uint32_t sB0 = (uint32_t)__cvta_generic_to_shared(Bsm)
                       + (uint32_t)(b_kb * BST + b_nc) * 4;
    const uint32_t aBufStride = A_SZ * 4;
    const uint32_t bBufStride = B_SZ * 4;
    const uint32_t aSlot = 32 * AST * 4;
    const uint32_t bSlot = 8 * BST * 4;

    const float* aBase = A + (size_t)(row0 + a_rb) * K + a_q;
    const float* bBase = B + (size_t)b_kb * N + col0 + b_nc;
    const size_t aGStride = (size_t)32 * K;
    const size_t bGStride = (size_t)8 * N;

    int az[4];
#pragma unroll
    for (int t = 0; t < 4; t++) az[t] = (row0 + a_rb + t * 32 < M) ? 16 : 0;

    float acc[4][4][4];
#pragma unroll
    for (int mi = 0; mi < 4; mi++)
#pragma unroll
        for (int ni = 0; ni < 4; ni++)
#pragma unroll
            for (int q = 0; q < 4; q++) acc[mi][ni][q] = 0.f;

    const int NT = K >> 5;

#define LOAD_TILE(buf, k0)                                                    \
    do {                                                                      \
        _Pragma("unroll")                                                     \
        for (int t = 0; t < 4; t++) {                                         \
            CP_ASYNC16(sA0 + (buf) * aBufStride + t * aSlot,                  \
                       aBase + t * aGStride + (k0), az[t]);                   \
            CP_ASYNC16(sB0 + (buf) * bBufStride + t * bSlot,                  \
                       bBase + t * bGStride + (size_t)(k0) * N, 16);          \
        }                                                                     \
    } while (0)

    LOAD_TILE(0, 0);
    CP_COMMIT();

    for (int it = 0; it < NT; it++) {
        const int cur = it & 1;
        if (it + 1 < NT) LOAD_TILE(cur ^ 1, (it + 1) << 5);
        CP_COMMIT();
        CP_WAIT1();
        __syncthreads();

        const uint32_t* Au = (const uint32_t*)(Asm + cur * A_SZ);
        const uint32_t* Bu = (const uint32_t*)(Bsm + cur * B_SZ);
#pragma unroll
        for (int ks = 0; ks < 4; ks++) {
            const int kb = ks * 8;
            uint32_t af[4][4];
#pragma unroll
            for (int mi = 0; mi < 4; mi++) {
                int r = wm + mi * 16 + g;
                af[mi][0] = Au[r * AST + kb + t4];
                af[mi][1] = Au[(r + 8) * AST + kb + t4];
                af[mi][2] = Au[r * AST + kb + t4 + 4];
                af[mi][3] = Au[(r + 8) * AST + kb + t4 + 4];
            }
            uint32_t bf[4][2];
#pragma unroll
            for (int ni = 0; ni < 4; ni++) {
                int n = wn + ni * 8 + g;
                bf[ni][0] = Bu[(kb + t4) * BST + n];
                bf[ni][1] = Bu[(kb + t4 + 4) * BST + n];
            }
#pragma unroll
            for (int mi = 0; mi < 4; mi++)
#pragma unroll
                for (int ni = 0; ni < 4; ni++)
                    mma_tf32(acc[mi][ni], af[mi], bf[ni], acc[mi][ni]);
        }
        __syncthreads();
    }

    // epilogue
#pragma unroll
    for (int mi = 0; mi < 4; mi++) {
        int r_lo = row0 + wm + mi * 16 + g;
        int r_hi = r_lo + 8;
#pragma unroll
        for (int ni = 0; ni < 4; ni++) {
            int c = col0 + wn + ni * 8 + t4 * 2;
            float badd0 = bias ? bias[c]     : 0.f;
            float badd1 = bias ? bias[c + 1] : 0.f;
            float v0 = acc[mi][ni][0] + badd0;
            float v1 = acc[mi][ni][1] + badd1;
            float v2 = acc[mi][ni][2] + badd0;
            float v3 = acc[mi][ni][3] + badd1;
            if (resid) {
                if (r_lo < M) {
                    v0 += resid[(size_t)r_lo * N + c];
                    v1 += resid[(size_t)r_lo * N + c + 1];
                }
                if (r_hi < M) {
                    v2 += resid[(size_t)r_hi * N + c];
                    v3 += resid[(size_t)r_hi * N + c + 1];
                }
            }
            if (relu) {
                v0 = fmaxf(v0, 0.f); v1 = fmaxf(v1, 0.f);
                v2 = fmaxf(v2, 0.f); v3 = fmaxf(v3, 0.f);
            }
            if (r_lo < M) {
                C[(size_t)r_lo * N + c]     = v0;
                C[(size_t)r_lo * N + c + 1] = v1;
            }
            if (r_hi < M) {
                C[(size_t)r_hi * N + c]     = v2;
                C[(size_t)r_hi * N + c + 1] = v3;
            }
        }
    }
#undef LOAD_TILE
}

// ---------------- attention scores (float4 loads) ------------------------------
__global__ void attn_scores(const float* __restrict__ h,
                            const float* __restrict__ av, const float* __restrict__ dv,
                            int H)
{
    int warp = (blockIdx.x * blockDim.x + threadIdx.x) >> 5;
    int lane = threadIdx.x & 31;
    if (warp >= NN) return;
    const float4* hr = (const float4*)(h + (size_t)warp * H);
    const float4* a4 = (const float4*)av;
    const float4* d4 = (const float4*)dv;
    float s1 = 0.f, s2 = 0.f;
    for (int k = lane; k < (H >> 2); k += 32) {
        float4 v = hr[k], a = a4[k], d = d4[k];
        s1 += v.x * a.x + v.y * a.y + v.z * a.z + v.w * a.w;
        s2 += v.x * d.x + v.y * d.y + v.z * d.z + v.w * d.w;
    }
#pragma unroll
    for (int o = 16; o; o >>= 1) {
        s1 += __shfl_down_sync(0xffffffffu, s1, o);
        s2 += __shfl_down_sync(0xffffffffu, s2, o);
    }
    if (lane == 0) { g_as[warp] = s1; g_ad[warp] = s2; }
}

// ---------------- GAT aggregation: 2 warps per node (feature split) ------------
// Each warp owns H/2 columns of one node. 2-edge unroll (R13-proven), no-max
// softmax; resid == nullptr -> raw agg mode. Deterministic: disjoint columns.
template <int H, bool RELU>
__global__ __launch_bounds__(256) void gat_agg_warp(
    const float* __restrict__ h, const float* __restrict__ resid,
    const float* __restrict__ bias, float* __restrict__ out)
{
    const int gw   = (int)((blockIdx.x * blockDim.x + threadIdx.x) >> 5);
    const int node = gw >> 1;
    const int part = gw & 1;
    const int lane = threadIdx.x & 31;
    if (node >= NN) return;
    const int beg = g_rowptr[node], end = g_rowptr[node + 1];
    const float adv = g_ad[node];
    constexpr int HH = H / 2;            // columns owned by this warp
    constexpr int V4 = HH / 128;         // float4 per lane (1 for H=256)
    const int coff = part * HH;          // column offset (floats)

    float4 acc[V4];
#pragma unroll
    for (int v = 0; v < V4; v++) acc[v] = make_float4(0.f, 0.f, 0.f, 0.f);
    float ssum = 0.f;

    for (int p = beg; p < end; p += 32) {
        int j = p + lane;
        float w = 0.f;
        int s = 0;
        if (j < end) {
            s = g_csr[j];
            float z = g_as[s] + adv;
            z = z > 0.f ? z : NEG_SLOPE * z;
            w = __expf(z);
        }
        ssum += w;
        int cnt = min(32, end - p);
        int t = 0;
        for (; t + 1 < cnt; t += 2) {
            float wt0 = __shfl_sync(0xffffffffu, w, t);
            int   st0 = __shfl_sync(0xffffffffu, s, t);
            float wt1 = __shfl_sync(0xffffffffu, w, t + 1);
            int   st1 = __shfl_sync(0xffffffffu, s, t + 1);
            const float4* h0 = (const float4*)(h + (size_t)st0 * H + coff);
            const float4* h1 = (const float4*)(h + (size_t)st1 * H + coff);
#pragma unroll
            for (int v = 0; v < V4; v++) {
                int i = lane + v * 32;
                float4 a0 = h0[i], a1 = h1[i];
                acc[v].x += wt0 * a0.x + wt1 * a1.x;
                acc[v].y += wt0 * a0.y + wt1 * a1.y;
                acc[v].z += wt0 * a0.z + wt1 * a1.z;
                acc[v].w += wt0 * a0.w + wt1 * a1.w;
            }
        }
        if (t < cnt) {
            float wt = __shfl_sync(0xffffffffu, w, t);
            int   st = __shfl_sync(0xffffffffu, s, t);
            const float4* hr = (const float4*)(h + (size_t)st * H + coff);
#pragma unroll
            for (int v = 0; v < V4; v++) {
                int i = lane + v * 32;
                float4 hv = hr[i];
                acc[v].x += wt * hv.x;
                acc[v].y += wt * hv.y;
                acc[v].z += wt * hv.z;
                acc[v].w += wt * hv.w;
            }
        }
    }
#pragma unroll
    for (int o = 16; o; o >>= 1) ssum += __shfl_xor_sync(0xffffffffu, ssum, o);
    float inv = 1.f / (ssum + 1e-16f);

    float4* o4 = (float4*)(out + (size_t)node * H + coff);
    if (resid) {
        const float4* r4 = (const float4*)(resid + (size_t)node * H + coff);
        const float4* b4 = (const float4*)(bias + coff);
#pragma unroll
        for (int v = 0; v < V4; v++) {
            int i = lane + v * 32;
            float4 rr = r4[i], bb = b4[i];
            float4 ov;
            ov.x = acc[v].x * inv + bb.x + rr.x;
            ov.y = acc[v].y * inv + bb.y + rr.y;
            ov.z = acc[v].z * inv + bb.z + rr.z;
            ov.w = acc[v].w * inv + bb.w + rr.w;
            if (RELU) {
                ov.x = fmaxf(ov.x, 0.f); ov.y = fmaxf(ov.y, 0.f);
                ov.z = fmaxf(ov.z, 0.f); ov.w = fmaxf(ov.w, 0.f);
            }
            o4[i] = ov;
        }
    } else {
#pragma unroll
        for (int v = 0; v < V4; v++) {
            int i = lane + v * 32;
            float4 ov;
            ov.x = acc[v].x * inv;
            ov.y = acc[v].y * inv;
            ov.z = acc[v].z * inv;
            ov.w = acc[v].w * inv;
            o4[i] = ov;
        }
    }
}

// ---------------- classifier + softmax (warp per node) -------------------------
__global__ void classifier_softmax(const float* __restrict__ h,
                                   const float* __restrict__ w,
                                   const float* __restrict__ b,
                                   float* __restrict__ out)
{
    int warp = (blockIdx.x * blockDim.x + threadIdx.x) >> 5;
    int lane = threadIdx.x & 31;
    if (warp >= NN) return;
    const float* hr = h + (size_t)warp * HC2;
    float d0 = 0, d1 = 0, d2 = 0, d3 = 0, d4 = 0;
    for (int k = lane; k < HC2; k += 32) {
        float v = hr[k];
        d0 += v * w[k * 5 + 0];
        d1 += v * w[k * 5 + 1];
        d2 += v * w[k * 5 + 2];
        d3 += v * w[k * 5 + 3];
        d4 += v * w[k * 5 + 4];
    }
#pragma unroll
    for (int o = 16; o; o >>= 1) {
        d0 += __shfl_down_sync(0xffffffffu, d0, o);
        d1 += __shfl_down_sync(0xffffffffu, d1, o);
        d2 += __shfl_down_sync(0xffffffffu, d2, o);
        d3 += __shfl_down_sync(0xffffffffu, d3, o);
        d4 += __shfl_down_sync(0xffffffffu, d4, o);
    }
    if (lane == 0) {
        d0 += b[0]; d1 += b[1]; d2 += b[2]; d3 += b[3]; d4 += b[4];
        float mx = fmaxf(fmaxf(fmaxf(d0, d1), fmaxf(d2, d3)), d4);
        float e0 = expf(d0 - mx), e1 = expf(d1 - mx), e2 = expf(d2 - mx),
              e3 = expf(d3 - mx), e4 = expf(d4 - mx);
        float inv = 1.f / (e0 + e1 + e2 + e3 + e4);
        out[warp * 5 + 0] = e0 * inv;
        out[warp * 5 + 1] = e1 * inv;
        out[warp * 5 + 2] = e2 * inv;
        out[warp * 5 + 3] = e3 * inv;
        out[warp * 5 + 4] = e4 * inv;
    }
}

// ---------------- launch -------------------------------------------------------
extern "C" void kernel_launch(void* const* d_in, const int* in_sizes, int n_in,
                              void* d_out, int out_size)
{
    const float* x        = (const float*)d_in[0];
    const void*  ei       = d_in[1];
    const float* W1       = (const float*)d_in[2];
    const float* att_src1 = (const float*)d_in[3];
    const float* att_dst1 = (const float*)d_in[4];
    const float* b_conv1  = (const float*)d_in[5];
    const float* A1       = (const float*)d_in[6];
    const float* b1       = (const float*)d_in[7];
    const float* W2       = (const float*)d_in[8];
    const float* att_src2 = (const float*)d_in[9];
    const float* att_dst2 = (const float*)d_in[10];
    const float* b_conv2  = (const float*)d_in[11];
    const float* A2       = (const float*)d_in[12];
    const float* b2       = (const float*)d_in[13];
    const float* Hw1      = (const float*)d_in[14];
    const float* Hb1      = (const float*)d_in[15];
    const float* Hw2      = (const float*)d_in[16];
    const float* Hb2      = (const float*)d_in[17];
    const float* Hw3      = (const float*)d_in[18];
    const float* Hb3      = (const float*)d_in[19];
    const float* fcw      = (const float*)d_in[20];
    const float* fcb      = (const float*)d_in[21];
    float* out = (float*)d_out;

    float *p_aggx, *p_r1, *p_hrelu, *p_h2, *p_r2, *p_g2, *p_m1, *p_m2;
    float *p_cs, *p_cd, *p_cs2, *p_cd2;
    cudaGetSymbolAddress((void**)&p_aggx,  g_aggx);
    cudaGetSymbolAddress((void**)&p_r1,    g_r1);
    cudaGetSymbolAddress((void**)&p_hrelu, g_hrelu);
    cudaGetSymbolAddress((void**)&p_h2,    g_h2);
    cudaGetSymbolAddress((void**)&p_r2,    g_r2);
    cudaGetSymbolAddress((void**)&p_g2,    g_g2);
    cudaGetSymbolAddress((void**)&p_m1,    g_m1);
    cudaGetSymbolAddress((void**)&p_m2,    g_m2);
    cudaGetSymbolAddress((void**)&p_cs,    g_cs);
    cudaGetSymbolAddress((void**)&p_cd,    g_cd);
    cudaGetSymbolAddress((void**)&p_cs2,   g_cs2);
    cudaGetSymbolAddress((void**)&p_cd2,   g_cd2);

    cudaFuncSetAttribute(gemm_tf32, cudaFuncAttributeMaxDynamicSharedMemorySize,
                         GEMM_SMEM);

    const int NB1024 = (NN + 1023) / 1024;
    const int MB = (NN + 127) / 128;
    const int warps_grid = (NN * 32 + 255) / 256;
    const int agg_grid = (NN * 2 * 32 + 255) / 256;   // 2 warps per node

    // single side stream (proven capture topology)
    cudaStream_t s1;
    cudaStreamCreateWithFlags(&s1, cudaStreamNonBlocking);
    cudaEvent_t e_fork, e_att1, e_join, e_h, e_att2;
    cudaEventCreateWithFlags(&e_fork, cudaEventDisableTiming);
    cudaEventCreateWithFlags(&e_att1, cudaEventDisableTiming);
    cudaEventCreateWithFlags(&e_join, cudaEventDisableTiming);
    cudaEventCreateWithFlags(&e_h,    cudaEventDisableTiming);
    cudaEventCreateWithFlags(&e_att2, cudaEventDisableTiming);

    cudaEventRecord(e_fork, 0);
    cudaStreamWaitEvent(s1, e_fork, 0);

    // ---- side stream: CSR build only ----
    detect_dtype<<<1, 256, 0, s1>>>((const int*)ei);
    zero_build<<<(NN + 255) / 256, 256, 0, s1>>>();
    convert_edges_count<<<(NE + 255) / 256, 256, 0, s1>>>(ei);
    scan_chunk<<<NB1024, 1024, 0, s1>>>();
    scan_bsums<<<1, 32, 0, s1>>>(NB1024);
    finalize_rowptr<<<NB1024, 1024, 0, s1>>>();
    scatter_csr<<<(NE + 255) / 256, 256, 0, s1>>>();

    // ---- main: layer-1 attention (no CSR needed), then r1 GEMM ----
    precompute_att<<<(DIN * 32 + 255) / 256, 256>>>(
        W1, att_src1, att_dst1, p_cs, p_cd, DIN, HC1);
    attn_scores<<<warps_grid, 256>>>(x, p_cs, p_cd, DIN);
    cudaEventRecord(e_att1, 0);

    gemm_tf32<<<dim3(HC1 / 128, MB), 256, GEMM_SMEM>>>(
        x, A1, nullptr, b1, nullptr, nullptr, nullptr, p_r1, nullptr,
        NN, HC1, DIN, 0);

    // ---- side stream: aggregate x (needs CSR + attn1) ----
    cudaStreamWaitEvent(s1, e_att1, 0);
    gat_agg_warp<DIN, false><<<agg_grid, 256, 0, s1>>>(
        x, nullptr, nullptr, p_aggx);
    cudaEventRecord(e_join, s1);

    cudaStreamWaitEvent(0, e_join, 0);

    // hrelu = relu(aggx@W1 + b_conv1 + r1)
    gemm_tf32<<<dim3(HC1 / 128, MB), 256, GEMM_SMEM>>>(
        p_aggx, W1, nullptr, b_conv1, nullptr, p_r1, nullptr, p_hrelu, nullptr,
        NN, HC1, DIN, 1);
    cudaEventRecord(e_h, 0);

    // ---- side stream: layer-2 collapsed attention on hrelu ----
    cudaStreamWaitEvent(s1, e_h, 0);
    precompute_att<<<(HC1 * 32 + 255) / 256, 256, 0, s1>>>(
        W2, att_src2, att_dst2, p_cs2, p_cd2, HC1, HC2);
    attn_scores<<<warps_grid, 256, 0, s1>>>(p_hrelu, p_cs2, p_cd2, HC1);
    cudaEventRecord(e_att2, s1);

    // ---- layer 2 dual GEMM (main, concurrent with attn2) ----
    gemm_tf32<<<dim3(2 * HC2 / 128, MB), 256, GEMM_SMEM>>>(
        p_hrelu, W2, A2, nullptr, b2, nullptr, nullptr, p_h2, p_r2,
        NN, HC2, HC1, 0);

    cudaStreamWaitEvent(0, e_att2, 0);
    gat_agg_warp<HC2, false><<<agg_grid, 256>>>(p_h2, p_r2, b_conv2, p_g2);

    // ---- MLP ----
    gemm_tf32<<<dim3(HC2 / 128, MB), 256, GEMM_SMEM>>>(
        p_g2, Hw1, nullptr, Hb1, nullptr, nullptr, nullptr, p_m1, nullptr,
        NN, HC2, HC2, 1);
    gemm_tf32<<<dim3(HC2 / 128, MB), 256, GEMM_SMEM>>>(
        p_m1, Hw2, nullptr, Hb2, nullptr, nullptr, nullptr, p_m2, nullptr,
        NN, HC2, HC2, 1);
    gemm_tf32<<<dim3(HC2 / 128, MB), 256, GEMM_SMEM>>>(
        p_m2, Hw3, nullptr, Hb3, nullptr, nullptr, nullptr, p_m1, nullptr,
        NN, HC2, HC2, 1);

    // ---- classifier + softmax ----
    classifier_softmax<<<warps_grid, 256>>>(p_m1, fcw, fcb, out);
}

// round 16
// speedup vs baseline: 1.0403x; 1.0268x over previous
#include <cuda_runtime.h>
#include <math.h>
#include <stdint.h>

#define NN   50000
#define NE   800000
#define DIN  256
#define HC1  512
#define HC2  256
#define NEG_SLOPE 0.2f

// ---------------- scratch (device globals; no allocation allowed) -------------
__device__ float g_aggx[NN * DIN];
__device__ float g_r1[NN * HC1];
__device__ float g_hrelu[NN * HC1];
__device__ float g_h2[NN * HC2];
__device__ float g_r2[NN * HC2];
__device__ float g_g2[NN * HC2];
__device__ float g_m1[NN * HC2];
__device__ float g_m2[NN * HC2];
__device__ float g_as[NN];
__device__ float g_ad[NN];
__device__ float g_cs[DIN];          // W1 @ att_src1
__device__ float g_cd[DIN];          // W1 @ att_dst1
__device__ float g_cs2[HC1];         // W2 @ att_src2
__device__ float g_cd2[HC1];         // W2 @ att_dst2
__device__ int   g_src[NE];
__device__ int   g_dst[NE];
__device__ int   g_csr[NE];
__device__ int   g_deg[NN];
__device__ int   g_cur[NN];
__device__ int   g_inc[NN];
__device__ int   g_bsum[256];
__device__ int   g_rowptr[NN + 1];
__device__ int   g_is64;

// ---------------- edge dtype detection + conversion ---------------------------
__global__ void detect_dtype(const int* __restrict__ ei) {
    __shared__ int nz;
    if (threadIdx.x == 0) nz = 0;
    __syncthreads();
    for (int t = threadIdx.x; t < 1024; t += blockDim.x) {
        long long pos = 1 + (long long)t * ((2LL * NE - 2) / 1024);
        pos |= 1;
        if (ei[pos] != 0) atomicExch(&nz, 1);
    }
    __syncthreads();
    if (threadIdx.x == 0) g_is64 = (nz == 0) ? 1 : 0;
}

__global__ void zero_build() {
    int i = blockIdx.x * blockDim.x + threadIdx.x;
    if (i < NN) { g_deg[i] = 0; g_cur[i] = 0; }
}

__global__ void convert_edges_count(const void* __restrict__ eiv) {
    int i = blockIdx.x * blockDim.x + threadIdx.x;
    if (i >= NE) return;
    int s, d;
    if (g_is64) {
        const long long* e = (const long long*)eiv;
        s = (int)e[i];
        d = (int)e[NE + i];
    } else {
        const int* e = (const int*)eiv;
        s = e[i];
        d = e[NE + i];
    }
    g_src[i] = s;
    g_dst[i] = d;
    atomicAdd(&g_deg[d], 1);
}

__global__ void scan_chunk() {
    __shared__ int s[1024];
    int tid = threadIdx.x;
    int i = blockIdx.x * 1024 + tid;
    int v = (i < NN) ? g_deg[i] : 0;
    s[tid] = v;
    __syncthreads();
    for (int off = 1; off < 1024; off <<= 1) {
        int t = (tid >= off) ? s[tid - off] : 0;
        __syncthreads();
        s[tid] += t;
        __syncthreads();
    }
    if (i < NN) g_inc[i] = s[tid];
    if (tid == 1023) g_bsum[blockIdx.x] = s[1023];
}

__global__ void scan_bsums(int nb) {
    if (threadIdx.x == 0 && blockIdx.x == 0) {
        int run = 0;
        for (int i = 0; i < nb; i++) { int v = g_bsum[i]; g_bsum[i] = run; run += v; }
    }
}

__global__ void finalize_rowptr() {
    int i = blockIdx.x * 1024 + threadIdx.x;
    if (i < NN) g_rowptr[i + 1] = g_inc[i] + g_bsum[blockIdx.x];
    if (i == 0) g_rowptr[0] = 0;
}

__global__ void scatter_csr() {
    int i = blockIdx.x * blockDim.x + threadIdx.x;
    if (i < NE) {
        int d = g_dst[i];
        int p = g_rowptr[d] + atomicAdd(&g_cur[d], 1);
        g_csr[p] = g_src[i];
    }
}

// ---------------- collapsed attention vectors: out = W @ attvec ----------------
__global__ void precompute_att(const float* __restrict__ W,
                               const float* __restrict__ avec,
                               const float* __restrict__ dvec,
                               float* __restrict__ outS,
                               float* __restrict__ outD,
                               int K, int H)
{
    int wk = (blockIdx.x * blockDim.x + threadIdx.x) >> 5;
    int lane = threadIdx.x & 31;
    if (wk >= K) return;
    const float* wr = W + (size_t)wk * H;
    float s1 = 0.f, s2 = 0.f;
    for (int j = lane; j < H; j += 32) {
        float v = wr[j];
        s1 += v * avec[j];
        s2 += v * dvec[j];
    }
#pragma unroll
    for (int o = 16; o; o >>= 1) {
        s1 += __shfl_down_sync(0xffffffffu, s1, o);
        s2 += __shfl_down_sync(0xffffffffu, s2, o);
    }
    if (lane == 0) { outS[wk] = s1; outD[wk] = s2; }
}

// ---------------- TF32 tensor-core GEMM, cp.async 2-stage, BK=32 ---------------
__device__ __forceinline__ void mma_tf32(float d[4], const uint32_t a[4],
                                         const uint32_t b[2], const float c[4]) {
    asm volatile(
        "mma.sync.aligned.m16n8k8.row.col.f32.tf32.tf32.f32 "
        "{%0,%1,%2,%3},{%4,%5,%6,%7},{%8,%9},{%10,%11,%12,%13};\n"
        : "=f"(d[0]), "=f"(d[1]), "=f"(d[2]), "=f"(d[3])
        : "r"(a[0]), "r"(a[1]), "r"(a[2]), "r"(a[3]),
          "r"(b[0]), "r"(b[1]),
          "f"(c[0]), "f"(c[1]), "f"(c[2]), "f"(c[3]));
}

#define AST 36
#define BST 136
#define A_SZ (128 * AST)
#define B_SZ (32 * BST)
#define GEMM_SMEM ((2 * A_SZ + 2 * B_SZ) * 4)

#define CP_ASYNC16(dst_u32, src_ptr, srcsz) \
    asm volatile("cp.async.cg.shared.global [%0], [%1], 16, %2;\n" \
                 :: "r"(dst_u32), "l"(src_ptr), "r"(srcsz))
#define CP_COMMIT() asm volatile("cp.async.commit_group;\n")
#define CP_WAIT1()  asm volatile("cp.async.wait_group 1;\n")

__global__ __launch_bounds__(256) void gemm_tf32(
    const float* __restrict__ A,
    const float* __restrict__ B1, const float* __restrict__ B2,
    const float* __restrict__ bias1, const float* __restrict__ bias2,
    const float* __restrict__ res1, const float* __restrict__ res2,
    float* __restrict__ C1, float* __restrict__ C2,
    int M, int N, int K, int relu)
{
    extern __shared__ float sm[];
    float* Asm = sm;
    float* Bsm = sm + 2 * A_SZ;

    const int tid  = threadIdx.x;
    const int lane = tid & 31;
    const int warp = tid >> 5;
    const int g    = lane >> 2;
    const int t4   = lane & 3;
    const int wm = (warp & 1) * 64;
    const int wn = (warp >> 1) * 32;

    const int nb = N >> 7;
    const int half = (B2 != nullptr && (int)blockIdx.x >= nb) ? 1 : 0;
    const float* B     = half ? B2    : B1;
    const float* bias  = half ? bias2 : bias1;
    const float* resid = half ? res2  : res1;
    float*       C     = half ? C2    : C1;
    const int col0 = (blockIdx.x - half * nb) * 128;
    const int row0 = blockIdx.y * 128;

    const int a_rb = tid >> 3;
    const int a_q  = (tid & 7) << 2;
    const int b_kb = tid >> 5;
    const int b_nc = (tid & 31) << 2;

    const uint32_t sA0 = (uint32_t)__cvta_generic_to_shared(Asm)
                       + (uint32_t)(a_rb * AST + a_q) * 4;
    const uint32_t sB0 = (uint32_t)__cvta_generic_to_shared(Bsm)
                       + (uint32_t)(b_kb * BST + b_nc) * 4;
    const uint32_t aBufStride = A_SZ * 4;
    const uint32_t bBufStride = B_SZ * 4;
    const uint32_t aSlot = 32 * AST * 4;
    const uint32_t bSlot = 8 * BST * 4;

    const float* aBase = A + (size_t)(row0 + a_rb) * K + a_q;
    const float* bBase = B + (size_t)b_kb * N + col0 + b_nc;
    const size_t aGStride = (size_t)32 * K;
    const size_t bGStride = (size_t)8 * N;

    int az[4];
#pragma unroll
    for (int t = 0; t < 4; t++) az[t] = (row0 + a_rb + t * 32 < M) ? 16 : 0;

    float acc[4][4][4];
#pragma unroll
    for (int mi = 0; mi < 4; mi++)
#pragma unroll
        for (int ni = 0; ni < 4; ni++)
#pragma unroll
            for (int q = 0; q < 4; q++) acc[mi][ni][q] = 0.f;

    const int NT = K >> 5;

#define LOAD_TILE(buf, k0)                                                    \
    do {                                                                      \
        _Pragma("unroll")                                                     \
        for (int t = 0; t < 4; t++) {                                         \
            CP_ASYNC16(sA0 + (buf) * aBufStride + t * aSlot,                  \
                       aBase + t * aGStride + (k0), az[t]);                   \
            CP_ASYNC16(sB0 + (buf) * bBufStride + t * bSlot,                  \
                       bBase + t * bGStride + (size_t)(k0) * N, 16);          \
        }                                                                     \
    } while (0)

    LOAD_TILE(0, 0);
    CP_COMMIT();

    for (int it = 0; it < NT; it++) {
        const int cur = it & 1;
        if (it + 1 < NT) LOAD_TILE(cur ^ 1, (it + 1) << 5);
        CP_COMMIT();
        CP_WAIT1();
        __syncthreads();

        const uint32_t* Au = (const uint32_t*)(Asm + cur * A_SZ);
        const uint32_t* Bu = (const uint32_t*)(Bsm + cur * B_SZ);
#pragma unroll
        for (int ks = 0; ks < 4; ks++) {
            const int kb = ks * 8;
            uint32_t af[4][4];
#pragma unroll
            for (int mi = 0; mi < 4; mi++) {
                int r = wm + mi * 16 + g;
                af[mi][0] = Au[r * AST + kb + t4];
                af[mi][1] = Au[(r + 8) * AST + kb + t4];
                af[mi][2] = Au[r * AST + kb + t4 + 4];
                af[mi][3] = Au[(r + 8) * AST + kb + t4 + 4];
            }
            uint32_t bf[4][2];
#pragma unroll
            for (int ni = 0; ni < 4; ni++) {
                int n = wn + ni * 8 + g;
                bf[ni][0] = Bu[(kb + t4) * BST + n];
                bf[ni][1] = Bu[(kb + t4 + 4) * BST + n];
            }
#pragma unroll
            for (int mi = 0; mi < 4; mi++)
#pragma unroll
                for (int ni = 0; ni < 4; ni++)
                    mma_tf32(acc[mi][ni], af[mi], bf[ni], acc[mi][ni]);
        }
        __syncthreads();
    }

    // epilogue
#pragma unroll
    for (int mi = 0; mi < 4; mi++) {
        int r_lo = row0 + wm + mi * 16 + g;
        int r_hi = r_lo + 8;
#pragma unroll
        for (int ni = 0; ni < 4; ni++) {
            int c = col0 + wn + ni * 8 + t4 * 2;
            float badd0 = bias ? bias[c]     : 0.f;
            float badd1 = bias ? bias[c + 1] : 0.f;
            float v0 = acc[mi][ni][0] + badd0;
            float v1 = acc[mi][ni][1] + badd1;
            float v2 = acc[mi][ni][2] + badd0;
            float v3 = acc[mi][ni][3] + badd1;
            if (resid) {
                if (r_lo < M) {
                    v0 += resid[(size_t)r_lo * N + c];
                    v1 += resid[(size_t)r_lo * N + c + 1];
                }
                if (r_hi < M) {
                    v2 += resid[(size_t)r_hi * N + c];
                    v3 += resid[(size_t)r_hi * N + c + 1];
                }
            }
            if (relu) {
                v0 = fmaxf(v0, 0.f); v1 = fmaxf(v1, 0.f);
                v2 = fmaxf(v2, 0.f); v3 = fmaxf(v3, 0.f);
            }
            if (r_lo < M) {
                C[(size_t)r_lo * N + c]     = v0;
                C[(size_t)r_lo * N + c + 1] = v1;
            }
            if (r_hi < M) {
                C[(size_t)r_hi * N + c]     = v2;
                C[(size_t)r_hi * N + c + 1] = v3;
            }
        }
    }
#undef LOAD_TILE
}

// ---------------- attention scores (float4 loads) ------------------------------
__global__ void attn_scores(const float* __restrict__ h,
                            const float* __restrict__ av, const float* __restrict__ dv,
                            int H)
{
    int warp = (blockIdx.x * blockDim.x + threadIdx.x) >> 5;
    int lane = threadIdx.x & 31;
    if (warp >= NN) return;
    const float4* hr = (const float4*)(h + (size_t)warp * H);
    const float4* a4 = (const float4*)av;
    const float4* d4 = (const float4*)dv;
    float s1 = 0.f, s2 = 0.f;
    for (int k = lane; k < (H >> 2); k += 32) {
        float4 v = hr[k], a = a4[k], d = d4[k];
        s1 += v.x * a.x + v.y * a.y + v.z * a.z + v.w * a.w;
        s2 += v.x * d.x + v.y * d.y + v.z * d.z + v.w * d.w;
    }
#pragma unroll
    for (int o = 16; o; o >>= 1) {
        s1 += __shfl_down_sync(0xffffffffu, s1, o);
        s2 += __shfl_down_sync(0xffffffffu, s2, o);
    }
    if (lane == 0) { g_as[warp] = s1; g_ad[warp] = s2; }
}

// ---------------- GAT aggregation: warp per node in [nodeBeg,nodeEnd) ----------
// R13-proven body: 2-edge unroll, no-max softmax; resid == nullptr -> raw mode.
template <int H, bool RELU>
__global__ __launch_bounds__(256) void gat_agg_warp(
    const float* __restrict__ h, const float* __restrict__ resid,
    const float* __restrict__ bias, float* __restrict__ out,
    int nodeBeg, int nodeEnd)
{
    const int node = nodeBeg + (int)((blockIdx.x * blockDim.x + threadIdx.x) >> 5);
    const int lane = threadIdx.x & 31;
    if (node >= nodeEnd) return;
    const int beg = g_rowptr[node], end = g_rowptr[node + 1];
    const float adv = g_ad[node];
    constexpr int V4 = H / 128;

    float4 acc[V4];
#pragma unroll
    for (int v = 0; v < V4; v++) acc[v] = make_float4(0.f, 0.f, 0.f, 0.f);
    float ssum = 0.f;

    for (int p = beg; p < end; p += 32) {
        int j = p + lane;
        float w = 0.f;
        int s = 0;
        if (j < end) {
            s = g_csr[j];
            float z = g_as[s] + adv;
            z = z > 0.f ? z : NEG_SLOPE * z;
            w = __expf(z);
        }
        ssum += w;
        int cnt = min(32, end - p);
        int t = 0;
        for (; t + 1 < cnt; t += 2) {
            float wt0 = __shfl_sync(0xffffffffu, w, t);
            int   st0 = __shfl_sync(0xffffffffu, s, t);
            float wt1 = __shfl_sync(0xffffffffu, w, t + 1);
            int   st1 = __shfl_sync(0xffffffffu, s, t + 1);
            const float4* h0 = (const float4*)(h + (size_t)st0 * H);
            const float4* h1 = (const float4*)(h + (size_t)st1 * H);
#pragma unroll
            for (int v = 0; v < V4; v++) {
                int i = lane + v * 32;
                float4 a0 = h0[i], a1 = h1[i];
                acc[v].x += wt0 * a0.x + wt1 * a1.x;
                acc[v].y += wt0 * a0.y + wt1 * a1.y;
                acc[v].z += wt0 * a0.z + wt1 * a1.z;
                acc[v].w += wt0 * a0.w + wt1 * a1.w;
            }
        }
        if (t < cnt) {
            float wt = __shfl_sync(0xffffffffu, w, t);
            int   st = __shfl_sync(0xffffffffu, s, t);
            const float4* hr = (const float4*)(h + (size_t)st * H);
#pragma unroll
            for (int v = 0; v < V4; v++) {
                int i = lane + v * 32;
                float4 hv = hr[i];
                acc[v].x += wt * hv.x;
                acc[v].y += wt * hv.y;
                acc[v].z += wt * hv.z;
                acc[v].w += wt * hv.w;
            }
        }
    }
#pragma unroll
    for (int o = 16; o; o >>= 1) ssum += __shfl_xor_sync(0xffffffffu, ssum, o);
    float inv = 1.f / (ssum + 1e-16f);

    float4* o4 = (float4*)(out + (size_t)node * H);
    if (resid) {
        const float4* r4 = (const float4*)(resid + (size_t)node * H);
        const float4* b4 = (const float4*)bias;
#pragma unroll
        for (int v = 0; v < V4; v++) {
            int i = lane + v * 32;
            float4 rr = r4[i], bb = b4[i];
            float4 ov;
            ov.x = acc[v].x * inv + bb.x + rr.x;
            ov.y = acc[v].y * inv + bb.y + rr.y;
            ov.z = acc[v].z * inv + bb.z + rr.z;
            ov.w = acc[v].w * inv + bb.w + rr.w;
            if (RELU) {
                ov.x = fmaxf(ov.x, 0.f); ov.y = fmaxf(ov.y, 0.f);
                ov.z = fmaxf(ov.z, 0.f); ov.w = fmaxf(ov.w, 0.f);
            }
            o4[i] = ov;
        }
    } else {
#pragma unroll
        for (int v = 0; v < V4; v++) {
            int i = lane + v * 32;
            float4 ov;
            ov.x = acc[v].x * inv;
            ov.y = acc[v].y * inv;
            ov.z = acc[v].z * inv;
            ov.w = acc[v].w * inv;
            o4[i] = ov;
        }
    }
}

// ---------------- classifier + softmax (warp per node) -------------------------
__global__ void classifier_softmax(const float* __restrict__ h,
                                   const float* __restrict__ w,
                                   const float* __restrict__ b,
                                   float* __restrict__ out)
{
    int warp = (blockIdx.x * blockDim.x + threadIdx.x) >> 5;
    int lane = threadIdx.x & 31;
    if (warp >= NN) return;
    const float* hr = h + (size_t)warp * HC2;
    float d0 = 0, d1 = 0, d2 = 0, d3 = 0, d4 = 0;
    for (int k = lane; k < HC2; k += 32) {
        float v = hr[k];
        d0 += v * w[k * 5 + 0];
        d1 += v * w[k * 5 + 1];
        d2 += v * w[k * 5 + 2];
        d3 += v * w[k * 5 + 3];
        d4 += v * w[k * 5 + 4];
    }
#pragma unroll
    for (int o = 16; o; o >>= 1) {
        d0 += __shfl_down_sync(0xffffffffu, d0, o);
        d1 += __shfl_down_sync(0xffffffffu, d1, o);
        d2 += __shfl_down_sync(0xffffffffu, d2, o);
        d3 += __shfl_down_sync(0xffffffffu, d3, o);
        d4 += __shfl_down_sync(0xffffffffu, d4, o);
    }
    if (lane == 0) {
        d0 += b[0]; d1 += b[1]; d2 += b[2]; d3 += b[3]; d4 += b[4];
        float mx = fmaxf(fmaxf(fmaxf(d0, d1), fmaxf(d2, d3)), d4);
        float e0 = expf(d0 - mx), e1 = expf(d1 - mx), e2 = expf(d2 - mx),
              e3 = expf(d3 - mx), e4 = expf(d4 - mx);
        float inv = 1.f / (e0 + e1 + e2 + e3 + e4);
        out[warp * 5 + 0] = e0 * inv;
        out[warp * 5 + 1] = e1 * inv;
        out[warp * 5 + 2] = e2 * inv;
        out[warp * 5 + 3] = e3 * inv;
        out[warp * 5 + 4] = e4 * inv;
    }
}

// ---------------- launch -------------------------------------------------------
extern "C" void kernel_launch(void* const* d_in, const int* in_sizes, int n_in,
                              void* d_out, int out_size)
{
    const float* x        = (const float*)d_in[0];
    const void*  ei       = d_in[1];
    const float* W1       = (const float*)d_in[2];
    const float* att_src1 = (const float*)d_in[3];
    const float* att_dst1 = (const float*)d_in[4];
    const float* b_conv1  = (const float*)d_in[5];
    const float* A1       = (const float*)d_in[6];
    const float* b1       = (const float*)d_in[7];
    const float* W2       = (const float*)d_in[8];
    const float* att_src2 = (const float*)d_in[9];
    const float* att_dst2 = (const float*)d_in[10];
    const float* b_conv2  = (const float*)d_in[11];
    const float* A2       = (const float*)d_in[12];
    const float* b2       = (const float*)d_in[13];
    const float* Hw1      = (const float*)d_in[14];
    const float* Hb1      = (const float*)d_in[15];
    const float* Hw2      = (const float*)d_in[16];
    const float* Hb2      = (const float*)d_in[17];
    const float* Hw3      = (const float*)d_in[18];
    const float* Hb3      = (const float*)d_in[19];
    const float* fcw      = (const float*)d_in[20];
    const float* fcb      = (const float*)d_in[21];
    float* out = (float*)d_out;

    float *p_aggx, *p_r1, *p_hrelu, *p_h2, *p_r2, *p_g2, *p_m1, *p_m2;
    float *p_cs, *p_cd, *p_cs2, *p_cd2;
    cudaGetSymbolAddress((void**)&p_aggx,  g_aggx);
    cudaGetSymbolAddress((void**)&p_r1,    g_r1);
    cudaGetSymbolAddress((void**)&p_hrelu, g_hrelu);
    cudaGetSymbolAddress((void**)&p_h2,    g_h2);
    cudaGetSymbolAddress((void**)&p_r2,    g_r2);
    cudaGetSymbolAddress((void**)&p_g2,    g_g2);
    cudaGetSymbolAddress((void**)&p_m1,    g_m1);
    cudaGetSymbolAddress((void**)&p_m2,    g_m2);
    cudaGetSymbolAddress((void**)&p_cs,    g_cs);
    cudaGetSymbolAddress((void**)&p_cd,    g_cd);
    cudaGetSymbolAddress((void**)&p_cs2,   g_cs2);
    cudaGetSymbolAddress((void**)&p_cd2,   g_cd2);

    cudaFuncSetAttribute(gemm_tf32, cudaFuncAttributeMaxDynamicSharedMemorySize,
                         GEMM_SMEM);

    const int NB1024 = (NN + 1023) / 1024;
    const int MB = (NN + 127) / 128;
    const int warps_grid = (NN * 32 + 255) / 256;
    const int NSPLIT = NN / 2;                          // side owns [0, NSPLIT)
    const int side_grid = (NSPLIT * 32 + 255) / 256;
    const int main_grid = ((NN - NSPLIT) * 32 + 255) / 256;

    // single side stream (proven capture topology)
    cudaStream_t s1;
    cudaStreamCreateWithFlags(&s1, cudaStreamNonBlocking);
    cudaEvent_t e_fork, e_att1, e_join, e_h, e_att2;
    cudaEventCreateWithFlags(&e_fork, cudaEventDisableTiming);
    cudaEventCreateWithFlags(&e_att1, cudaEventDisableTiming);
    cudaEventCreateWithFlags(&e_join, cudaEventDisableTiming);
    cudaEventCreateWithFlags(&e_h,    cudaEventDisableTiming);
    cudaEventCreateWithFlags(&e_att2, cudaEventDisableTiming);

    cudaEventRecord(e_fork, 0);
    cudaStreamWaitEvent(s1, e_fork, 0);

    // ---- side stream: CSR build ----
    detect_dtype<<<1, 256, 0, s1>>>((const int*)ei);
    zero_build<<<(NN + 255) / 256, 256, 0, s1>>>();
    convert_edges_count<<<(NE + 255) / 256, 256, 0, s1>>>(ei);
    scan_chunk<<<NB1024, 1024, 0, s1>>>();
    scan_bsums<<<1, 32, 0, s1>>>(NB1024);
    finalize_rowptr<<<NB1024, 1024, 0, s1>>>();
    scatter_csr<<<(NE + 255) / 256, 256, 0, s1>>>();

    // ---- main: layer-1 attention (no CSR needed), then r1 GEMM ----
    precompute_att<<<(DIN * 32 + 255) / 256, 256>>>(
        W1, att_src1, att_dst1, p_cs, p_cd, DIN, HC1);
    attn_scores<<<warps_grid, 256>>>(x, p_cs, p_cd, DIN);
    cudaEventRecord(e_att1, 0);

    gemm_tf32<<<dim3(HC1 / 128, MB), 256, GEMM_SMEM>>>(
        x, A1, nullptr, b1, nullptr, nullptr, nullptr, p_r1, nullptr,
        NN, HC1, DIN, 0);

    // ---- agg1 split: side half concurrent with r1 GEMM, main half after ----
    cudaStreamWaitEvent(s1, e_att1, 0);
    gat_agg_warp<DIN, false><<<side_grid, 256, 0, s1>>>(
        x, nullptr, nullptr, p_aggx, 0, NSPLIT);
    cudaEventRecord(e_join, s1);

    gat_agg_warp<DIN, false><<<main_grid, 256>>>(
        x, nullptr, nullptr, p_aggx, NSPLIT, NN);

    cudaStreamWaitEvent(0, e_join, 0);

    // hrelu = relu(aggx@W1 + b_conv1 + r1)
    gemm_tf32<<<dim3(HC1 / 128, MB), 256, GEMM_SMEM>>>(
        p_aggx, W1, nullptr, b_conv1, nullptr, p_r1, nullptr, p_hrelu, nullptr,
        NN, HC1, DIN, 1);
    cudaEventRecord(e_h, 0);

    // ---- side stream: layer-2 collapsed attention on hrelu ----
    cudaStreamWaitEvent(s1, e_h, 0);
    precompute_att<<<(HC1 * 32 + 255) / 256, 256, 0, s1>>>(
        W2, att_src2, att_dst2, p_cs2, p_cd2, HC1, HC2);
    attn_scores<<<warps_grid, 256, 0, s1>>>(p_hrelu, p_cs2, p_cd2, HC1);
    cudaEventRecord(e_att2, s1);

    // ---- layer 2 dual GEMM (main, concurrent with attn2) ----
    gemm_tf32<<<dim3(2 * HC2 / 128, MB), 256, GEMM_SMEM>>>(
        p_hrelu, W2, A2, nullptr, b2, nullptr, nullptr, p_h2, p_r2,
        NN, HC2, HC1, 0);

    cudaStreamWaitEvent(0, e_att2, 0);
    gat_agg_warp<HC2, false><<<warps_grid, 256>>>(
        p_h2, p_r2, b_conv2, p_g2, 0, NN);

    // ---- MLP ----
    gemm_tf32<<<dim3(HC2 / 128, MB), 256, GEMM_SMEM>>>(
        p_g2, Hw1, nullptr, Hb1, nullptr, nullptr, nullptr, p_m1, nullptr,
        NN, HC2, HC2, 1);
    gemm_tf32<<<dim3(HC2 / 128, MB), 256, GEMM_SMEM>>>(
        p_m1, Hw2, nullptr, Hb2, nullptr, nullptr, nullptr, p_m2, nullptr,
        NN, HC2, HC2, 1);
    gemm_tf32<<<dim3(HC2 / 128, MB), 256, GEMM_SMEM>>>(
        p_m2, Hw3, nullptr, Hb3, nullptr, nullptr, nullptr, p_m1, nullptr,
        NN, HC2, HC2, 1);

    // ---- classifier + softmax ----
    classifier_softmax<<<warps_grid, 256>>>(p_m1, fcw, fcb, out);
}

// round 17
// speedup vs baseline: 1.0899x; 1.0477x over previous
#include <cuda_runtime.h>
#include <math.h>
#include <stdint.h>

#define NN   50000
#define NE   800000
#define DIN  256
#define HC1  512
#define HC2  256
#define NEG_SLOPE 0.2f

// ---------------- scratch (device globals; no allocation allowed) -------------
__device__ float g_aggx[NN * DIN];
__device__ float g_r1[NN * HC1];
__device__ float g_hrelu[NN * HC1];
__device__ float g_h2[NN * HC2];
__device__ float g_r2[NN * HC2];
__device__ float g_g2[NN * HC2];
__device__ float g_m1[NN * HC2];
__device__ float g_m2[NN * HC2];
__device__ float g_as[NN];
__device__ float g_ad[NN];
__device__ float g_cs[DIN];          // W1 @ att_src1
__device__ float g_cd[DIN];          // W1 @ att_dst1
__device__ float g_cs2[HC1];         // W2 @ att_src2
__device__ float g_cd2[HC1];         // W2 @ att_dst2
__device__ int   g_src[NE];
__device__ int   g_dst[NE];
__device__ int   g_csr[NE];
__device__ int   g_deg[NN];
__device__ int   g_cur[NN];
__device__ int   g_inc[NN];
__device__ int   g_bsum[256];
__device__ int   g_rowptr[NN + 1];
__device__ int   g_is64;

// ---------------- edge dtype detection + conversion ---------------------------
__global__ void detect_dtype(const int* __restrict__ ei) {
    __shared__ int nz;
    if (threadIdx.x == 0) nz = 0;
    __syncthreads();
    for (int t = threadIdx.x; t < 1024; t += blockDim.x) {
        long long pos = 1 + (long long)t * ((2LL * NE - 2) / 1024);
        pos |= 1;
        if (ei[pos] != 0) atomicExch(&nz, 1);
    }
    __syncthreads();
    if (threadIdx.x == 0) g_is64 = (nz == 0) ? 1 : 0;
}

__global__ void zero_build() {
    int i = blockIdx.x * blockDim.x + threadIdx.x;
    if (i < NN) { g_deg[i] = 0; g_cur[i] = 0; }
}

__global__ void convert_edges_count(const void* __restrict__ eiv) {
    int i = blockIdx.x * blockDim.x + threadIdx.x;
    if (i >= NE) return;
    int s, d;
    if (g_is64) {
        const long long* e = (const long long*)eiv;
        s = (int)e[i];
        d = (int)e[NE + i];
    } else {
        const int* e = (const int*)eiv;
        s = e[i];
        d = e[NE + i];
    }
    g_src[i] = s;
    g_dst[i] = d;
    atomicAdd(&g_deg[d], 1);
}

__global__ void scan_chunk() {
    __shared__ int s[1024];
    int tid = threadIdx.x;
    int i = blockIdx.x * 1024 + tid;
    int v = (i < NN) ? g_deg[i] : 0;
    s[tid] = v;
    __syncthreads();
    for (int off = 1; off < 1024; off <<= 1) {
        int t = (tid >= off) ? s[tid - off] : 0;
        __syncthreads();
        s[tid] += t;
        __syncthreads();
    }
    if (i < NN) g_inc[i] = s[tid];
    if (tid == 1023) g_bsum[blockIdx.x] = s[1023];
}

__global__ void scan_bsums(int nb) {
    if (threadIdx.x == 0 && blockIdx.x == 0) {
        int run = 0;
        for (int i = 0; i < nb; i++) { int v = g_bsum[i]; g_bsum[i] = run; run += v; }
    }
}

__global__ void finalize_rowptr() {
    int i = blockIdx.x * 1024 + threadIdx.x;
    if (i < NN) g_rowptr[i + 1] = g_inc[i] + g_bsum[blockIdx.x];
    if (i == 0) g_rowptr[0] = 0;
}

__global__ void scatter_csr() {
    int i = blockIdx.x * blockDim.x + threadIdx.x;
    if (i < NE) {
        int d = g_dst[i];
        int p = g_rowptr[d] + atomicAdd(&g_cur[d], 1);
        g_csr[p] = g_src[i];
    }
}

// ---------------- collapsed attention vectors: out = W @ attvec ----------------
__global__ void precompute_att(const float* __restrict__ W,
                               const float* __restrict__ avec,
                               const float* __restrict__ dvec,
                               float* __restrict__ outS,
                               float* __restrict__ outD,
                               int K, int H)
{
    int wk = (blockIdx.x * blockDim.x + threadIdx.x) >> 5;
    int lane = threadIdx.x & 31;
    if (wk >= K) return;
    const float* wr = W + (size_t)wk * H;
    float s1 = 0.f, s2 = 0.f;
    for (int j = lane; j < H; j += 32) {
        float v = wr[j];
        s1 += v * avec[j];
        s2 += v * dvec[j];
    }
#pragma unroll
    for (int o = 16; o; o >>= 1) {
        s1 += __shfl_down_sync(0xffffffffu, s1, o);
        s2 += __shfl_down_sync(0xffffffffu, s2, o);
    }
    if (lane == 0) { outS[wk] = s1; outD[wk] = s2; }
}

// ---------------- TF32 tensor-core GEMM, cp.async 2-stage, BK=32 ---------------
__device__ __forceinline__ void mma_tf32(float d[4], const uint32_t a[4],
                                         const uint32_t b[2], const float c[4]) {
    asm volatile(
        "mma.sync.aligned.m16n8k8.row.col.f32.tf32.tf32.f32 "
        "{%0,%1,%2,%3},{%4,%5,%6,%7},{%8,%9},{%10,%11,%12,%13};\n"
        : "=f"(d[0]), "=f"(d[1]), "=f"(d[2]), "=f"(d[3])
        : "r"(a[0]), "r"(a[1]), "r"(a[2]), "r"(a[3]),
          "r"(b[0]), "r"(b[1]),
          "f"(c[0]), "f"(c[1]), "f"(c[2]), "f"(c[3]));
}

#define AST 36
#define BST 136
#define A_SZ (128 * AST)
#define B_SZ (32 * BST)
#define GEMM_SMEM ((2 * A_SZ + 2 * B_SZ) * 4)

#define CP_ASYNC16(dst_u32, src_ptr, srcsz) \
    asm volatile("cp.async.cg.shared.global [%0], [%1], 16, %2;\n" \
                 :: "r"(dst_u32), "l"(src_ptr), "r"(srcsz))
#define CP_COMMIT() asm volatile("cp.async.commit_group;\n")
#define CP_WAIT1()  asm volatile("cp.async.wait_group 1;\n")

__global__ __launch_bounds__(256) void gemm_tf32(
    const float* __restrict__ A,
    const float* __restrict__ B1, const float* __restrict__ B2,
    const float* __restrict__ bias1, const float* __restrict__ bias2,
    const float* __restrict__ res1, const float* __restrict__ res2,
    float* __restrict__ C1, float* __restrict__ C2,
    int M, int N, int K, int relu)
{
    extern __shared__ float sm[];
    float* Asm = sm;
    float* Bsm = sm + 2 * A_SZ;

    const int tid  = threadIdx.x;
    const int lane = tid & 31;
    const int warp = tid >> 5;
    const int g    = lane >> 2;
    const int t4   = lane & 3;
    const int wm = (warp & 1) * 64;
    const int wn = (warp >> 1) * 32;

    const int nb = N >> 7;
    const int half = (B2 != nullptr && (int)blockIdx.x >= nb) ? 1 : 0;
    const float* B     = half ? B2    : B1;
    const float* bias  = half ? bias2 : bias1;
    const float* resid = half ? res2  : res1;
    float*       C     = half ? C2    : C1;
    const int col0 = (blockIdx.x - half * nb) * 128;
    const int row0 = blockIdx.y * 128;

    const int a_rb = tid >> 3;
    const int a_q  = (tid & 7) << 2;
    const int b_kb = tid >> 5;
    const int b_nc = (tid & 31) << 2;

    const uint32_t sA0 = (uint32_t)__cvta_generic_to_shared(Asm)
                       + (uint32_t)(a_rb * AST + a_q) * 4;
    const uint32_t sB0 = (uint32_t)__cvta_generic_to_shared(Bsm)
                       + (uint32_t)(b_kb * BST + b_nc) * 4;
    const uint32_t aBufStride = A_SZ * 4;
    const uint32_t bBufStride = B_SZ * 4;
    const uint32_t aSlot = 32 * AST * 4;
    const uint32_t bSlot = 8 * BST * 4;

    const float* aBase = A + (size_t)(row0 + a_rb) * K + a_q;
    const float* bBase = B + (size_t)b_kb * N + col0 + b_nc;
    const size_t aGStride = (size_t)32 * K;
    const size_t bGStride = (size_t)8 * N;

    int az[4];
#pragma unroll
    for (int t = 0; t < 4; t++) az[t] = (row0 + a_rb + t * 32 < M) ? 16 : 0;

    float acc[4][4][4];
#pragma unroll
    for (int mi = 0; mi < 4; mi++)
#pragma unroll
        for (int ni = 0; ni < 4; ni++)
#pragma unroll
            for (int q = 0; q < 4; q++) acc[mi][ni][q] = 0.f;

    const int NT = K >> 5;

#define LOAD_TILE(buf, k0)                                                    \
    do {                                                                      \
        _Pragma("unroll")                                                     \
        for (int t = 0; t < 4; t++) {                                         \
            CP_ASYNC16(sA0 + (buf) * aBufStride + t * aSlot,                  \
                       aBase + t * aGStride + (k0), az[t]);                   \
            CP_ASYNC16(sB0 + (buf) * bBufStride + t * bSlot,                  \
                       bBase + t * bGStride + (size_t)(k0) * N, 16);          \
        }                                                                     \
    } while (0)

    LOAD_TILE(0, 0);
    CP_COMMIT();

    for (int it = 0; it < NT; it++) {
        const int cur = it & 1;
        if (it + 1 < NT) LOAD_TILE(cur ^ 1, (it + 1) << 5);
        CP_COMMIT();
        CP_WAIT1();
        __syncthreads();

        const uint32_t* Au = (const uint32_t*)(Asm + cur * A_SZ);
        const uint32_t* Bu = (const uint32_t*)(Bsm + cur * B_SZ);
#pragma unroll
        for (int ks = 0; ks < 4; ks++) {
            const int kb = ks * 8;
            uint32_t af[4][4];
#pragma unroll
            for (int mi = 0; mi < 4; mi++) {
                int r = wm + mi * 16 + g;
                af[mi][0] = Au[r * AST + kb + t4];
                af[mi][1] = Au[(r + 8) * AST + kb + t4];
                af[mi][2] = Au[r * AST + kb + t4 + 4];
                af[mi][3] = Au[(r + 8) * AST + kb + t4 + 4];
            }
            uint32_t bf[4][2];
#pragma unroll
            for (int ni = 0; ni < 4; ni++) {
                int n = wn + ni * 8 + g;
                bf[ni][0] = Bu[(kb + t4) * BST + n];
                bf[ni][1] = Bu[(kb + t4 + 4) * BST + n];
            }
#pragma unroll
            for (int mi = 0; mi < 4; mi++)
#pragma unroll
                for (int ni = 0; ni < 4; ni++)
                    mma_tf32(acc[mi][ni], af[mi], bf[ni], acc[mi][ni]);
        }
        __syncthreads();
    }

    // epilogue
#pragma unroll
    for (int mi = 0; mi < 4; mi++) {
        int r_lo = row0 + wm + mi * 16 + g;
        int r_hi = r_lo + 8;
#pragma unroll
        for (int ni = 0; ni < 4; ni++) {
            int c = col0 + wn + ni * 8 + t4 * 2;
            float badd0 = bias ? bias[c]     : 0.f;
            float badd1 = bias ? bias[c + 1] : 0.f;
            float v0 = acc[mi][ni][0] + badd0;
            float v1 = acc[mi][ni][1] + badd1;
            float v2 = acc[mi][ni][2] + badd0;
            float v3 = acc[mi][ni][3] + badd1;
            if (resid) {
                if (r_lo < M) {
                    v0 += resid[(size_t)r_lo * N + c];
                    v1 += resid[(size_t)r_lo * N + c + 1];
                }
                if (r_hi < M) {
                    v2 += resid[(size_t)r_hi * N + c];
                    v3 += resid[(size_t)r_hi * N + c + 1];
                }
            }
            if (relu) {
                v0 = fmaxf(v0, 0.f); v1 = fmaxf(v1, 0.f);
                v2 = fmaxf(v2, 0.f); v3 = fmaxf(v3, 0.f);
            }
            if (r_lo < M) {
                C[(size_t)r_lo * N + c]     = v0;
                C[(size_t)r_lo * N + c + 1] = v1;
            }
            if (r_hi < M) {
                C[(size_t)r_hi * N + c]     = v2;
                C[(size_t)r_hi * N + c + 1] = v3;
            }
        }
    }
#undef LOAD_TILE
}

// ---------------- attention scores (float4 loads) ------------------------------
__global__ void attn_scores(const float* __restrict__ h,
                            const float* __restrict__ av, const float* __restrict__ dv,
                            int H)
{
    int warp = (blockIdx.x * blockDim.x + threadIdx.x) >> 5;
    int lane = threadIdx.x & 31;
    if (warp >= NN) return;
    const float4* hr = (const float4*)(h + (size_t)warp * H);
    const float4* a4 = (const float4*)av;
    const float4* d4 = (const float4*)dv;
    float s1 = 0.f, s2 = 0.f;
    for (int k = lane; k < (H >> 2); k += 32) {
        float4 v = hr[k], a = a4[k], d = d4[k];
        s1 += v.x * a.x + v.y * a.y + v.z * a.z + v.w * a.w;
        s2 += v.x * d.x + v.y * d.y + v.z * d.z + v.w * d.w;
    }
#pragma unroll
    for (int o = 16; o; o >>= 1) {
        s1 += __shfl_down_sync(0xffffffffu, s1, o);
        s2 += __shfl_down_sync(0xffffffffu, s2, o);
    }
    if (lane == 0) { g_as[warp] = s1; g_ad[warp] = s2; }
}

// ---------------- GAT aggregation: warp per node in [nodeBeg,nodeEnd) ----------
// R13-proven body: 2-edge unroll, no-max softmax; resid == nullptr -> raw mode.
template <int H, bool RELU>
__global__ __launch_bounds__(256) void gat_agg_warp(
    const float* __restrict__ h, const float* __restrict__ resid,
    const float* __restrict__ bias, float* __restrict__ out,
    int nodeBeg, int nodeEnd)
{
    const int node = nodeBeg + (int)((blockIdx.x * blockDim.x + threadIdx.x) >> 5);
    const int lane = threadIdx.x & 31;
    if (node >= nodeEnd) return;
    const int beg = g_rowptr[node], end = g_rowptr[node + 1];
    const float adv = g_ad[node];
    constexpr int V4 = H / 128;

    float4 acc[V4];
#pragma unroll
    for (int v = 0; v < V4; v++) acc[v] = make_float4(0.f, 0.f, 0.f, 0.f);
    float ssum = 0.f;

    for (int p = beg; p < end; p += 32) {
        int j = p + lane;
        float w = 0.f;
        int s = 0;
        if (j < end) {
            s = g_csr[j];
            float z = g_as[s] + adv;
            z = z > 0.f ? z : NEG_SLOPE * z;
            w = __expf(z);
        }
        ssum += w;
        int cnt = min(32, end - p);
        int t = 0;
        for (; t + 1 < cnt; t += 2) {
            float wt0 = __shfl_sync(0xffffffffu, w, t);
            int   st0 = __shfl_sync(0xffffffffu, s, t);
            float wt1 = __shfl_sync(0xffffffffu, w, t + 1);
            int   st1 = __shfl_sync(0xffffffffu, s, t + 1);
            const float4* h0 = (const float4*)(h + (size_t)st0 * H);
            const float4* h1 = (const float4*)(h + (size_t)st1 * H);
#pragma unroll
            for (int v = 0; v < V4; v++) {
                int i = lane + v * 32;
                float4 a0 = h0[i], a1 = h1[i];
                acc[v].x += wt0 * a0.x + wt1 * a1.x;
                acc[v].y += wt0 * a0.y + wt1 * a1.y;
                acc[v].z += wt0 * a0.z + wt1 * a1.z;
                acc[v].w += wt0 * a0.w + wt1 * a1.w;
            }
        }
        if (t < cnt) {
            float wt = __shfl_sync(0xffffffffu, w, t);
            int   st = __shfl_sync(0xffffffffu, s, t);
            const float4* hr = (const float4*)(h + (size_t)st * H);
#pragma unroll
            for (int v = 0; v < V4; v++) {
                int i = lane + v * 32;
                float4 hv = hr[i];
                acc[v].x += wt * hv.x;
                acc[v].y += wt * hv.y;
                acc[v].z += wt * hv.z;
                acc[v].w += wt * hv.w;
            }
        }
    }
#pragma unroll
    for (int o = 16; o; o >>= 1) ssum += __shfl_xor_sync(0xffffffffu, ssum, o);
    float inv = 1.f / (ssum + 1e-16f);

    float4* o4 = (float4*)(out + (size_t)node * H);
    if (resid) {
        const float4* r4 = (const float4*)(resid + (size_t)node * H);
        const float4* b4 = (const float4*)bias;
#pragma unroll
        for (int v = 0; v < V4; v++) {
            int i = lane + v * 32;
            float4 rr = r4[i], bb = b4[i];
            float4 ov;
            ov.x = acc[v].x * inv + bb.x + rr.x;
            ov.y = acc[v].y * inv + bb.y + rr.y;
            ov.z = acc[v].z * inv + bb.z + rr.z;
            ov.w = acc[v].w * inv + bb.w + rr.w;
            if (RELU) {
                ov.x = fmaxf(ov.x, 0.f); ov.y = fmaxf(ov.y, 0.f);
                ov.z = fmaxf(ov.z, 0.f); ov.w = fmaxf(ov.w, 0.f);
            }
            o4[i] = ov;
        }
    } else {
#pragma unroll
        for (int v = 0; v < V4; v++) {
            int i = lane + v * 32;
            float4 ov;
            ov.x = acc[v].x * inv;
            ov.y = acc[v].y * inv;
            ov.z = acc[v].z * inv;
            ov.w = acc[v].w * inv;
            o4[i] = ov;
        }
    }
}

// ---------------- classifier + softmax (warp per node, nNodes rows) ------------
__global__ void classifier_softmax(const float* __restrict__ h,
                                   const float* __restrict__ w,
                                   const float* __restrict__ b,
                                   float* __restrict__ out,
                                   int nNodes)
{
    int warp = (blockIdx.x * blockDim.x + threadIdx.x) >> 5;
    int lane = threadIdx.x & 31;
    if (warp >= nNodes) return;
    const float* hr = h + (size_t)warp * HC2;
    float d0 = 0, d1 = 0, d2 = 0, d3 = 0, d4 = 0;
    for (int k = lane; k < HC2; k += 32) {
        float v = hr[k];
        d0 += v * w[k * 5 + 0];
        d1 += v * w[k * 5 + 1];
        d2 += v * w[k * 5 + 2];
        d3 += v * w[k * 5 + 3];
        d4 += v * w[k * 5 + 4];
    }
#pragma unroll
    for (int o = 16; o; o >>= 1) {
        d0 += __shfl_down_sync(0xffffffffu, d0, o);
        d1 += __shfl_down_sync(0xffffffffu, d1, o);
        d2 += __shfl_down_sync(0xffffffffu, d2, o);
        d3 += __shfl_down_sync(0xffffffffu, d3, o);
        d4 += __shfl_down_sync(0xffffffffu, d4, o);
    }
    if (lane == 0) {
        d0 += b[0]; d1 += b[1]; d2 += b[2]; d3 += b[3]; d4 += b[4];
        float mx = fmaxf(fmaxf(fmaxf(d0, d1), fmaxf(d2, d3)), d4);
        float e0 = expf(d0 - mx), e1 = expf(d1 - mx), e2 = expf(d2 - mx),
              e3 = expf(d3 - mx), e4 = expf(d4 - mx);
        float inv = 1.f / (e0 + e1 + e2 + e3 + e4);
        out[warp * 5 + 0] = e0 * inv;
        out[warp * 5 + 1] = e1 * inv;
        out[warp * 5 + 2] = e2 * inv;
        out[warp * 5 + 3] = e3 * inv;
        out[warp * 5 + 4] = e4 * inv;
    }
}

// ---------------- launch -------------------------------------------------------
extern "C" void kernel_launch(void* const* d_in, const int* in_sizes, int n_in,
                              void* d_out, int out_size)
{
    const float* x        = (const float*)d_in[0];
    const void*  ei       = d_in[1];
    const float* W1       = (const float*)d_in[2];
    const float* att_src1 = (const float*)d_in[3];
    const float* att_dst1 = (const float*)d_in[4];
    const float* b_conv1  = (const float*)d_in[5];
    const float* A1       = (const float*)d_in[6];
    const float* b1       = (const float*)d_in[7];
    const float* W2       = (const float*)d_in[8];
    const float* att_src2 = (const float*)d_in[9];
    const float* att_dst2 = (const float*)d_in[10];
    const float* b_conv2  = (const float*)d_in[11];
    const float* A2       = (const float*)d_in[12];
    const float* b2       = (const float*)d_in[13];
    const float* Hw1      = (const float*)d_in[14];
    const float* Hb1      = (const float*)d_in[15];
    const float* Hw2      = (const float*)d_in[16];
    const float* Hb2      = (const float*)d_in[17];
    const float* Hw3      = (const float*)d_in[18];
    const float* Hb3      = (const float*)d_in[19];
    const float* fcw      = (const float*)d_in[20];
    const float* fcb      = (const float*)d_in[21];
    float* out = (float*)d_out;

    float *p_aggx, *p_r1, *p_hrelu, *p_h2, *p_r2, *p_g2, *p_m1, *p_m2;
    float *p_cs, *p_cd, *p_cs2, *p_cd2;
    cudaGetSymbolAddress((void**)&p_aggx,  g_aggx);
    cudaGetSymbolAddress((void**)&p_r1,    g_r1);
    cudaGetSymbolAddress((void**)&p_hrelu, g_hrelu);
    cudaGetSymbolAddress((void**)&p_h2,    g_h2);
    cudaGetSymbolAddress((void**)&p_r2,    g_r2);
    cudaGetSymbolAddress((void**)&p_g2,    g_g2);
    cudaGetSymbolAddress((void**)&p_m1,    g_m1);
    cudaGetSymbolAddress((void**)&p_m2,    g_m2);
    cudaGetSymbolAddress((void**)&p_cs,    g_cs);
    cudaGetSymbolAddress((void**)&p_cd,    g_cd);
    cudaGetSymbolAddress((void**)&p_cs2,   g_cs2);
    cudaGetSymbolAddress((void**)&p_cd2,   g_cd2);

    cudaFuncSetAttribute(gemm_tf32, cudaFuncAttributeMaxDynamicSharedMemorySize,
                         GEMM_SMEM);

    const int NB1024 = (NN + 1023) / 1024;
    const int MB = (NN + 127) / 128;
    const int warps_grid = (NN * 32 + 255) / 256;
    const int NSPLIT = NN / 2;                          // agg1 side range
    const int side_grid = (NSPLIT * 32 + 255) / 256;
    const int main_grid = ((NN - NSPLIT) * 32 + 255) / 256;
    // tail pipelining: rows [0, NH) on main, [NH, NN) on side
    const int NH = NN / 2;                              // 25000
    const int MBH = (NH + 127) / 128;                   // 196
    const int half_warps = (NH * 32 + 255) / 256;

    cudaStream_t s1;
    cudaStreamCreateWithFlags(&s1, cudaStreamNonBlocking);
    cudaEvent_t e_fork, e_att1, e_join, e_h, e_att2, e_l2, e_done;
    cudaEventCreateWithFlags(&e_fork, cudaEventDisableTiming);
    cudaEventCreateWithFlags(&e_att1, cudaEventDisableTiming);
    cudaEventCreateWithFlags(&e_join, cudaEventDisableTiming);
    cudaEventCreateWithFlags(&e_h,    cudaEventDisableTiming);
    cudaEventCreateWithFlags(&e_att2, cudaEventDisableTiming);
    cudaEventCreateWithFlags(&e_l2,   cudaEventDisableTiming);
    cudaEventCreateWithFlags(&e_done, cudaEventDisableTiming);

    cudaEventRecord(e_fork, 0);
    cudaStreamWaitEvent(s1, e_fork, 0);

    // ---- side stream: CSR build ----
    detect_dtype<<<1, 256, 0, s1>>>((const int*)ei);
    zero_build<<<(NN + 255) / 256, 256, 0, s1>>>();
    convert_edges_count<<<(NE + 255) / 256, 256, 0, s1>>>(ei);
    scan_chunk<<<NB1024, 1024, 0, s1>>>();
    scan_bsums<<<1, 32, 0, s1>>>(NB1024);
    finalize_rowptr<<<NB1024, 1024, 0, s1>>>();
    scatter_csr<<<(NE + 255) / 256, 256, 0, s1>>>();

    // ---- main: layer-1 attention, then r1 GEMM ----
    precompute_att<<<(DIN * 32 + 255) / 256, 256>>>(
        W1, att_src1, att_dst1, p_cs, p_cd, DIN, HC1);
    attn_scores<<<warps_grid, 256>>>(x, p_cs, p_cd, DIN);
    cudaEventRecord(e_att1, 0);

    gemm_tf32<<<dim3(HC1 / 128, MB), 256, GEMM_SMEM>>>(
        x, A1, nullptr, b1, nullptr, nullptr, nullptr, p_r1, nullptr,
        NN, HC1, DIN, 0);

    // ---- agg1 split: side half concurrent with r1 GEMM, main half after ----
    cudaStreamWaitEvent(s1, e_att1, 0);
    gat_agg_warp<DIN, false><<<side_grid, 256, 0, s1>>>(
        x, nullptr, nullptr, p_aggx, 0, NSPLIT);
    cudaEventRecord(e_join, s1);

    gat_agg_warp<DIN, false><<<main_grid, 256>>>(
        x, nullptr, nullptr, p_aggx, NSPLIT, NN);

    cudaStreamWaitEvent(0, e_join, 0);

    // hrelu = relu(aggx@W1 + b_conv1 + r1)
    gemm_tf32<<<dim3(HC1 / 128, MB), 256, GEMM_SMEM>>>(
        p_aggx, W1, nullptr, b_conv1, nullptr, p_r1, nullptr, p_hrelu, nullptr,
        NN, HC1, DIN, 1);
    cudaEventRecord(e_h, 0);

    // ---- side stream: layer-2 collapsed attention on hrelu ----
    cudaStreamWaitEvent(s1, e_h, 0);
    precompute_att<<<(HC1 * 32 + 255) / 256, 256, 0, s1>>>(
        W2, att_src2, att_dst2, p_cs2, p_cd2, HC1, HC2);
    attn_scores<<<warps_grid, 256, 0, s1>>>(p_hrelu, p_cs2, p_cd2, HC1);
    cudaEventRecord(e_att2, s1);

    // ---- layer 2 dual GEMM (main, concurrent with attn2) ----
    gemm_tf32<<<dim3(2 * HC2 / 128, MB), 256, GEMM_SMEM>>>(
        p_hrelu, W2, A2, nullptr, b2, nullptr, nullptr, p_h2, p_r2,
        NN, HC2, HC1, 0);
    cudaEventRecord(e_l2, 0);

    // ---- tail pipelined in two row halves --------------------------------
    // main half: rows [0, NH)
    cudaStreamWaitEvent(0, e_att2, 0);
    gat_agg_warp<HC2, false><<<half_warps, 256>>>(
        p_h2, p_r2, b_conv2, p_g2, 0, NH);
    gemm_tf32<<<dim3(HC2 / 128, MBH), 256, GEMM_SMEM>>>(
        p_g2, Hw1, nullptr, Hb1, nullptr, nullptr, nullptr, p_m1, nullptr,
        NH, HC2, HC2, 1);
    gemm_tf32<<<dim3(HC2 / 128, MBH), 256, GEMM_SMEM>>>(
        p_m1, Hw2, nullptr, Hb2, nullptr, nullptr, nullptr, p_m2, nullptr,
        NH, HC2, HC2, 1);
    gemm_tf32<<<dim3(HC2 / 128, MBH), 256, GEMM_SMEM>>>(
        p_m2, Hw3, nullptr, Hb3, nullptr, nullptr, nullptr, p_m1, nullptr,
        NH, HC2, HC2, 1);
    classifier_softmax<<<half_warps, 256>>>(p_m1, fcw, fcb, out, NH);

    // side half: rows [NH, NN) (after L2 GEMM; attn2 in-order on side)
    cudaStreamWaitEvent(s1, e_l2, 0);
    gat_agg_warp<HC2, false><<<half_warps, 256, 0, s1>>>(
        p_h2, p_r2, b_conv2, p_g2, NH, NN);
    {
        const float* gB = p_g2 + (size_t)NH * HC2;
        float* m1B = p_m1 + (size_t)NH * HC2;
        float* m2B = p_m2 + (size_t)NH * HC2;
        gemm_tf32<<<dim3(HC2 / 128, MBH), 256, GEMM_SMEM, s1>>>(
            gB, Hw1, nullptr, Hb1, nullptr, nullptr, nullptr, m1B, nullptr,
            NN - NH, HC2, HC2, 1);
        gemm_tf32<<<dim3(HC2 / 128, MBH), 256, GEMM_SMEM, s1>>>(
            m1B, Hw2, nullptr, Hb2, nullptr, nullptr, nullptr, m2B, nullptr,
            NN - NH, HC2, HC2, 1);
        gemm_tf32<<<dim3(HC2 / 128, MBH), 256, GEMM_SMEM, s1>>>(
            m2B, Hw3, nullptr, Hb3, nullptr, nullptr, nullptr, m1B, nullptr,
            NN - NH, HC2, HC2, 1);
        classifier_softmax<<<half_warps, 256, 0, s1>>>(
            m1B, fcw, fcb, out + (size_t)NH * 5, NN - NH);
    }
    cudaEventRecord(e_done, s1);
    cudaStreamWaitEvent(0, e_done, 0);
}